// round 8
// baseline (speedup 1.0000x reference)
#include <cuda_runtime.h>
#include <math.h>

#define HID 1024
#define LEN 40
#define VOC 50257
#define NPART 6283            // ceil(VOC/8)

// block ranges inside the megakernel
#define B_COMB   1
#define B_LSTM0  129          // 1 + 128
#define B_LSTM1  641          // + 512
#define B_LOGI   1153         // + 512
#define NBLOCKS  (B_LOGI + NPART)

// ---- scratch (no allocations allowed) ----
__device__ float g_concat[3 * HID];   // [embedded ; attn_applied]
__device__ float g_x[HID];            // relu(comb) output
__device__ float g_hl0[HID];          // layer-0 hidden out
__device__ float g_hl1[HID];          // layer-1 hidden out
__device__ float g_pm[NPART];         // per-block logit max
__device__ float g_ps[NPART];         // per-block expsum
__device__ float g_lse[1];
__device__ int   g_c_attn, g_c_x, g_c_h0, g_c_h1;   // stage counters

__device__ __forceinline__ float warp_reduce(float s) {
#pragma unroll
    for (int o = 16; o; o >>= 1) s += __shfl_down_sync(0xFFFFFFFFu, s, o);
    return s;
}

__device__ __forceinline__ float dot4(float4 a, float4 b) {
    return a.x * b.x + a.y * b.y + a.z * b.z + a.w * b.w;
}

// Four consecutive streaming LDG.128 (stride 512 B) in one asm block:
// back-to-back issue, register-resident results => guaranteed MLP.
__device__ __forceinline__ void ldg4x4(const float4* p,
                                       float4& a, float4& b, float4& c, float4& d) {
    asm volatile(
        "ld.global.cs.v4.f32 {%0,%1,%2,%3}, [%16];\n\t"
        "ld.global.cs.v4.f32 {%4,%5,%6,%7}, [%16+512];\n\t"
        "ld.global.cs.v4.f32 {%8,%9,%10,%11}, [%16+1024];\n\t"
        "ld.global.cs.v4.f32 {%12,%13,%14,%15}, [%16+1536];"
        : "=f"(a.x), "=f"(a.y), "=f"(a.z), "=f"(a.w),
          "=f"(b.x), "=f"(b.y), "=f"(b.z), "=f"(b.w),
          "=f"(c.x), "=f"(c.y), "=f"(c.z), "=f"(c.w),
          "=f"(d.x), "=f"(d.y), "=f"(d.z), "=f"(d.w)
        : "l"(p));
}

// 1024-float row dot against vector v4 (8 loads in flight).
__device__ __forceinline__ float row_dot_1k(const float4* w, const float4* v4, int lane) {
    float4 w0, w1, w2, w3, w4, w5, w6, w7;
    ldg4x4(w + lane,       w0, w1, w2, w3);
    ldg4x4(w + lane + 128, w4, w5, w6, w7);
    float sA = dot4(v4[lane],       w0) + dot4(v4[lane + 32],  w1)
             + dot4(v4[lane + 64],  w2) + dot4(v4[lane + 96],  w3);
    float sB = dot4(v4[lane + 128], w4) + dot4(v4[lane + 160], w5)
             + dot4(v4[lane + 192], w6) + dot4(v4[lane + 224], w7);
    return sA + sB;
}

// consumer-side stage wait: thread 0 spins, whole block syncs, then fence
__device__ __forceinline__ void wait_stage(int* ctr, int target) {
    if (threadIdx.x == 0) {
        while (*(volatile int*)ctr < target) __nanosleep(64);
    }
    __syncthreads();
    __threadfence();
}

// producer-side stage arrive (call from ONE thread after block's data stores
// are fenced)
__device__ __forceinline__ void arrive_stage(int* ctr) {
    __threadfence();
    atomicAdd(ctr, 1);
}

__global__ void k_reset() {
    g_c_attn = 0; g_c_x = 0; g_c_h0 = 0; g_c_h1 = 0;
}

// ---------------------------------------------------------------------------
// Megakernel: attn | comb | lstm0 | lstm1 | logits, staged by blockIdx.x.
// Dependencies flow strictly from lower to higher block IDs.
// ---------------------------------------------------------------------------
__global__ void __launch_bounds__(256, 3)
k_mega(const int* __restrict__ tok,
       const float* __restrict__ h0,
       const float* __restrict__ c0,
       const float* __restrict__ enc,
       const float* __restrict__ emb,
       const float* __restrict__ attn_w,
       const float* __restrict__ attn_b,
       const float* __restrict__ comb_w,
       const float* __restrict__ comb_b,
       const float* __restrict__ w_ih0,
       const float* __restrict__ w_hh0,
       const float* __restrict__ b_ih0,
       const float* __restrict__ b_hh0,
       const float* __restrict__ w_ih1,
       const float* __restrict__ w_hh1,
       const float* __restrict__ b_ih1,
       const float* __restrict__ b_hh1,
       const float* __restrict__ out_w,
       const float* __restrict__ out_b,
       float* __restrict__ o_logp,
       float* __restrict__ o_h,
       float* __restrict__ o_c,
       float* __restrict__ o_attn) {
    int bid = blockIdx.x;
    int t = threadIdx.x;
    int wid = t >> 5, lane = t & 31;

    if (bid == 0) {
        // ---------------- attention (256 threads) ----------------
        __shared__ float s_ain[3 * HID];
        __shared__ float s_log[LEN];
        __shared__ float s_w[LEN];
        int token = tok[0];
        for (int i = t; i < HID; i += 256) {
            s_ain[i]           = emb[(size_t)token * HID + i];
            s_ain[HID + i]     = h0[i];
            s_ain[2 * HID + i] = h0[HID + i];
        }
        __syncthreads();

        for (int l = wid; l < LEN; l += 8) {
            const float4* w = (const float4*)(attn_w + (size_t)l * 3 * HID);
            const float4* a = (const float4*)s_ain;
            float s = 0.f;
#pragma unroll
            for (int c = 0; c < 3; c++) {
                float4 w0, w1, w2, w3, w4, w5, w6, w7;
                const float4* base = w + lane + 256 * c;
                ldg4x4(base,       w0, w1, w2, w3);
                ldg4x4(base + 128, w4, w5, w6, w7);
                int i0 = lane + 256 * c;
                s += dot4(a[i0],       w0) + dot4(a[i0 + 32],  w1)
                   + dot4(a[i0 + 64],  w2) + dot4(a[i0 + 96],  w3)
                   + dot4(a[i0 + 128], w4) + dot4(a[i0 + 160], w5)
                   + dot4(a[i0 + 192], w6) + dot4(a[i0 + 224], w7);
            }
            s = warp_reduce(s);
            if (lane == 0) s_log[l] = s + attn_b[l];
        }
        __syncthreads();

        if (t == 0) {
            float m = s_log[0];
            for (int l = 1; l < LEN; l++) m = fmaxf(m, s_log[l]);
            float sum = 0.f;
            for (int l = 0; l < LEN; l++) { float e = expf(s_log[l] - m); s_w[l] = e; sum += e; }
            float inv = 1.f / sum;
            for (int l = 0; l < LEN; l++) { s_w[l] *= inv; o_attn[l] = s_w[l]; }
        }
        __syncthreads();

        for (int j = t; j < 2 * HID; j += 256) {
            float s = 0.f;
#pragma unroll
            for (int l = 0; l < LEN; l++) s += s_w[l] * enc[l * 2 * HID + j];
            g_concat[HID + j] = s;
        }
        for (int i = t; i < HID; i += 256) g_concat[i] = s_ain[i];
        __syncthreads();
        if (t == 0) arrive_stage(&g_c_attn);

    } else if (bid < B_LSTM0) {
        // ---------------- comb: 8 warps x 1 row, 128 blocks ----------------
        int row = (bid - B_COMB) * 8 + wid;
        wait_stage(&g_c_attn, 1);
        const float4* w = (const float4*)(comb_w + (size_t)row * 3 * HID);
        const float4* v = (const float4*)g_concat;
        float s = 0.f;
#pragma unroll
        for (int c = 0; c < 3; c++)
            s += row_dot_1k(w + 256 * c, v + 256 * c, lane);
        s = warp_reduce(s);
        if (lane == 0) g_x[row] = fmaxf(s + comb_b[row], 0.f);
        __syncthreads();
        if (t == 0) arrive_stage(&g_c_x);

    } else if (bid < B_LOGI) {
        // ---------------- lstm layer 0 or 1: 2 units/block ----------------
        int layer = (bid >= B_LSTM1);
        int base  = layer ? B_LSTM1 : B_LSTM0;
        int u = (bid - base) * 2 + (wid >> 2);
        int gate = wid & 3;
        int row = gate * HID + u;
        const float* w_ih = layer ? w_ih1 : w_ih0;
        const float* w_hh = layer ? w_hh1 : w_hh0;
        const float* b_ih = layer ? b_ih1 : b_ih0;
        const float* b_hh = layer ? b_hh1 : b_hh0;
        const float* cprev = c0 + layer * HID;
        __shared__ float s_g[8];

        // phase A: w_hh·h_prev — depends only on inputs, runs before the spin
        const float4* wh = (const float4*)(w_hh + (size_t)row * HID);
        const float4* h4 = (const float4*)(h0 + layer * HID);
        float s_hh = warp_reduce(row_dot_1k(wh, h4, lane));

        // phase B: wait for x, then w_ih·x
        if (layer) wait_stage(&g_c_h0, 512);
        else       wait_stage(&g_c_x, 128);
        const float4* wi = (const float4*)(w_ih + (size_t)row * HID);
        const float4* x4 = (const float4*)(layer ? g_hl0 : g_x);
        float s_ih = warp_reduce(row_dot_1k(wi, x4, lane));
        if (lane == 0) s_g[wid] = s_ih + s_hh + b_ih[row] + b_hh[row];
        __syncthreads();

        if (t < 2) {
            int u2 = (bid - base) * 2 + t;
            int b = t * 4;
            float gi = s_g[b + 0], gf = s_g[b + 1], gg = s_g[b + 2], go = s_g[b + 3];
            float si = 1.f / (1.f + expf(-gi));
            float sf = 1.f / (1.f + expf(-gf));
            float so = 1.f / (1.f + expf(-go));
            float c2 = sf * cprev[u2] + si * tanhf(gg);
            float h2 = so * tanhf(c2);
            o_c[layer * HID + u2] = c2;
            o_h[layer * HID + u2] = h2;
            if (layer) g_hl1[u2] = h2; else g_hl0[u2] = h2;
        }
        __syncthreads();
        if (t == 0) arrive_stage(layer ? &g_c_h1 : &g_c_h0);

    } else {
        // ---------------- logits: 8 rows/block ----------------
        __shared__ float s_l[8];
        int pb = bid - B_LOGI;
        int r = pb * 8 + wid;
        wait_stage(&g_c_h1, 512);
        if (r < VOC) {
            const float4* w = (const float4*)(out_w + (size_t)r * HID);
            const float4* h4 = (const float4*)g_hl1;
            float s = warp_reduce(row_dot_1k(w, h4, lane));
            if (lane == 0) {
                float lg = s + out_b[r];
                o_logp[r] = lg;
                s_l[wid] = lg;
            }
        } else if (lane == 0) {
            s_l[wid] = -INFINITY;
        }
        __syncthreads();
        if (t == 0) {
            float m = s_l[0];
#pragma unroll
            for (int k = 1; k < 8; k++) m = fmaxf(m, s_l[k]);
            float sum = 0.f;
#pragma unroll
            for (int k = 0; k < 8; k++) sum += expf(s_l[k] - m);
            g_pm[pb] = m;
            g_ps[pb] = sum;
        }
    }
}

// ---------------------------------------------------------------------------
// combine per-block partials into log-sum-exp (single block)
// ---------------------------------------------------------------------------
__global__ void __launch_bounds__(1024, 1)
k_lse(void) {
    __shared__ float red[1024];
    int t = threadIdx.x;
    float m = -INFINITY;
    for (int i = t; i < NPART; i += 1024) m = fmaxf(m, g_pm[i]);
    red[t] = m;
    __syncthreads();
    for (int o = 512; o; o >>= 1) {
        if (t < o) red[t] = fmaxf(red[t], red[t + o]);
        __syncthreads();
    }
    m = red[0];
    __syncthreads();
    float s = 0.f;
    for (int i = t; i < NPART; i += 1024) s += g_ps[i] * expf(g_pm[i] - m);
    red[t] = s;
    __syncthreads();
    for (int o = 512; o; o >>= 1) {
        if (t < o) red[t] += red[t + o];
        __syncthreads();
    }
    if (t == 0) g_lse[0] = m + logf(red[0]);
}

__global__ void __launch_bounds__(256)
k_sub(float* __restrict__ logits) {
    int i = blockIdx.x * blockDim.x + threadIdx.x;
    float lse = g_lse[0];
    if (i < VOC) logits[i] -= lse;
}

// ---------------------------------------------------------------------------
// Output layout: [log_probs(V) | h_new(2*H) | c_new(2*H) | attn_weights(L)]
// ---------------------------------------------------------------------------
extern "C" void kernel_launch(void* const* d_in, const int* in_sizes, int n_in,
                              void* d_out, int out_size) {
    const int*   tok    = (const int*)  d_in[0];
    const float* h0     = (const float*)d_in[1];
    const float* c0     = (const float*)d_in[2];
    const float* enc    = (const float*)d_in[3];
    const float* emb    = (const float*)d_in[4];
    const float* attn_w = (const float*)d_in[5];
    const float* attn_b = (const float*)d_in[6];
    const float* comb_w = (const float*)d_in[7];
    const float* comb_b = (const float*)d_in[8];
    const float* w_ih0  = (const float*)d_in[9];
    const float* w_hh0  = (const float*)d_in[10];
    const float* b_ih0  = (const float*)d_in[11];
    const float* b_hh0  = (const float*)d_in[12];
    const float* w_ih1  = (const float*)d_in[13];
    const float* w_hh1  = (const float*)d_in[14];
    const float* b_ih1  = (const float*)d_in[15];
    const float* b_hh1  = (const float*)d_in[16];
    const float* out_w  = (const float*)d_in[17];
    const float* out_b  = (const float*)d_in[18];

    float* out      = (float*)d_out;
    float* o_logp   = out;
    float* o_h      = out + VOC;
    float* o_c      = out + VOC + 2 * HID;
    float* o_attn   = out + VOC + 4 * HID;

    k_reset<<<1, 1>>>();
    k_mega<<<NBLOCKS, 256>>>(tok, h0, c0, enc, emb, attn_w, attn_b,
                             comb_w, comb_b,
                             w_ih0, w_hh0, b_ih0, b_hh0,
                             w_ih1, w_hh1, b_ih1, b_hh1,
                             out_w, out_b,
                             o_logp, o_h, o_c, o_attn);
    k_lse<<<1, 1024>>>();
    k_sub<<<(VOC + 255) / 256, 256>>>(o_logp);
}

// round 9
// speedup vs baseline: 1.0759x; 1.0759x over previous
#include <cuda_runtime.h>
#include <math.h>

#define HID 1024
#define LEN 40
#define VOC 50257
#define NPART 6283   // ceil(VOC/8)

// ---- scratch (no allocations allowed) ----
__device__ float g_concat[3 * HID];   // [embedded ; attn_applied]
__device__ float g_x[HID];            // relu(comb) output
__device__ float g_hl0[HID];          // layer-0 hidden out
__device__ float g_hl1[HID];          // layer-1 hidden out
__device__ float g_hh[8 * HID];       // w_hh·h_prev partials, both layers
__device__ float g_pm[NPART];         // per-block logit max
__device__ float g_ps[NPART];         // per-block expsum

__device__ __forceinline__ float warp_reduce(float s) {
#pragma unroll
    for (int o = 16; o; o >>= 1) s += __shfl_down_sync(0xFFFFFFFFu, s, o);
    return s;
}

__device__ __forceinline__ float dot4(float4 a, float4 b) {
    return a.x * b.x + a.y * b.y + a.z * b.z + a.w * b.w;
}

// Four consecutive streaming LDG.128 (stride 512 B) in one asm block:
// back-to-back issue, register-resident results => guaranteed MLP.
__device__ __forceinline__ void ldg4x4(const float4* p,
                                       float4& a, float4& b, float4& c, float4& d) {
    asm volatile(
        "ld.global.cs.v4.f32 {%0,%1,%2,%3}, [%16];\n\t"
        "ld.global.cs.v4.f32 {%4,%5,%6,%7}, [%16+512];\n\t"
        "ld.global.cs.v4.f32 {%8,%9,%10,%11}, [%16+1024];\n\t"
        "ld.global.cs.v4.f32 {%12,%13,%14,%15}, [%16+1536];"
        : "=f"(a.x), "=f"(a.y), "=f"(a.z), "=f"(a.w),
          "=f"(b.x), "=f"(b.y), "=f"(b.z), "=f"(b.w),
          "=f"(c.x), "=f"(c.y), "=f"(c.z), "=f"(c.w),
          "=f"(d.x), "=f"(d.y), "=f"(d.z), "=f"(d.w)
        : "l"(p));
}

// 1024-float row dot against vector v4 (8 loads in flight).
__device__ __forceinline__ float row_dot_1k(const float4* w, const float4* v4, int lane) {
    float4 w0, w1, w2, w3, w4, w5, w6, w7;
    ldg4x4(w + lane,       w0, w1, w2, w3);
    ldg4x4(w + lane + 128, w4, w5, w6, w7);
    float sA = dot4(v4[lane],       w0) + dot4(v4[lane + 32],  w1)
             + dot4(v4[lane + 64],  w2) + dot4(v4[lane + 96],  w3);
    float sB = dot4(v4[lane + 128], w4) + dot4(v4[lane + 160], w5)
             + dot4(v4[lane + 192], w6) + dot4(v4[lane + 224], w7);
    return sA + sB;
}

// ---------------------------------------------------------------------------
// K0 (side branch): w_hh partials for BOTH layers. 8192 rows, warp per row.
// ---------------------------------------------------------------------------
__global__ void __launch_bounds__(256)
k_whh(const float* __restrict__ h0,
      const float* __restrict__ w_hh0,
      const float* __restrict__ w_hh1) {
    int t = threadIdx.x;
    int wid = t >> 5, lane = t & 31;
    int r = blockIdx.x * 8 + wid;                 // 0..8191
    int layer = r >> 12;
    int row = r & 4095;
    const float* w_hh = layer ? w_hh1 : w_hh0;
    const float4* w = (const float4*)(w_hh + (size_t)row * HID);
    const float4* h4 = (const float4*)(h0 + layer * HID);
    float s = warp_reduce(row_dot_1k(w, h4, lane));
    if (lane == 0) g_hh[r] = s;
}

// ---------------------------------------------------------------------------
// K1: embedding gather + attention logits + softmax + context (one block)
// ---------------------------------------------------------------------------
__global__ void __launch_bounds__(512)
k_attn(const int* __restrict__ tok,
       const float* __restrict__ h0,
       const float* __restrict__ emb,
       const float* __restrict__ attn_w,
       const float* __restrict__ attn_b,
       const float* __restrict__ enc,
       float* __restrict__ out_attnw) {
    __shared__ float s_ain[3 * HID];
    __shared__ float s_log[LEN];
    __shared__ float s_w[LEN];
    int t = threadIdx.x;            // 512 threads
    int token = tok[0];
    for (int i = t; i < HID; i += 512) {
        s_ain[i]           = emb[(size_t)token * HID + i];
        s_ain[HID + i]     = h0[i];
        s_ain[2 * HID + i] = h0[HID + i];
    }
    __syncthreads();

    int warp = t >> 5, lane = t & 31;   // 16 warps
    for (int l = warp; l < LEN; l += 16) {
        const float4* w = (const float4*)(attn_w + (size_t)l * 3 * HID);
        const float4* a = (const float4*)s_ain;
        float s = 0.f;
#pragma unroll
        for (int c = 0; c < 3; c++) {
            float4 w0, w1, w2, w3, w4, w5, w6, w7;
            const float4* base = w + lane + 256 * c;
            ldg4x4(base,       w0, w1, w2, w3);
            ldg4x4(base + 128, w4, w5, w6, w7);
            int i0 = lane + 256 * c;
            s += dot4(a[i0],       w0) + dot4(a[i0 + 32],  w1)
               + dot4(a[i0 + 64],  w2) + dot4(a[i0 + 96],  w3)
               + dot4(a[i0 + 128], w4) + dot4(a[i0 + 160], w5)
               + dot4(a[i0 + 192], w6) + dot4(a[i0 + 224], w7);
        }
        s = warp_reduce(s);
        if (lane == 0) s_log[l] = s + attn_b[l];
    }
    __syncthreads();

    if (t == 0) {
        float m = s_log[0];
        for (int l = 1; l < LEN; l++) m = fmaxf(m, s_log[l]);
        float sum = 0.f;
        for (int l = 0; l < LEN; l++) { float e = expf(s_log[l] - m); s_w[l] = e; sum += e; }
        float inv = 1.f / sum;
        for (int l = 0; l < LEN; l++) { s_w[l] *= inv; out_attnw[l] = s_w[l]; }
    }
    __syncthreads();

    // attn_applied[j] = sum_l w[l] * enc[l, j]
    for (int j = t; j < 2 * HID; j += 512) {
        float s = 0.f;
#pragma unroll
        for (int l = 0; l < LEN; l++) s += s_w[l] * enc[l * 2 * HID + j];
        g_concat[HID + j] = s;
    }
    for (int i = t; i < HID; i += 512) g_concat[i] = s_ain[i];
}

// ---------------------------------------------------------------------------
// K2: x = relu([emb;attn] @ comb_w.T + comb_b) — warp per row
// ---------------------------------------------------------------------------
__global__ void __launch_bounds__(256)
k_comb(const float* __restrict__ comb_w,
       const float* __restrict__ comb_b) {
    int t = threadIdx.x;
    int wid = t >> 5, lane = t & 31;
    int row = blockIdx.x * 8 + wid;      // 128 blocks x 8 warps = 1024 rows
    const float4* w = (const float4*)(comb_w + (size_t)row * 3 * HID);
    const float4* v = (const float4*)g_concat;
    float s = 0.f;
#pragma unroll
    for (int c = 0; c < 3; c++)
        s += row_dot_1k(w + 256 * c, v + 256 * c, lane);
    s = warp_reduce(s);
    if (lane == 0) g_x[row] = fmaxf(s + comb_b[row], 0.f);
}

// ---------------------------------------------------------------------------
// K3: LSTM w_ih matvec + combine (w_hh part precomputed in g_hh).
// 512 blocks x 256 thr; warps 0-3: unit0 gates, warps 4-7: unit1 gates.
// ---------------------------------------------------------------------------
__global__ void __launch_bounds__(256)
k_lstm(int layer,
       const float* __restrict__ cprev,
       const float* __restrict__ w_ih,
       const float* __restrict__ b_ih,
       const float* __restrict__ b_hh,
       float* __restrict__ h_out,
       float* __restrict__ c_out) {
    __shared__ float s_g[8];
    int t = threadIdx.x;
    int wid = t >> 5, lane = t & 31;
    int u = blockIdx.x * 2 + (wid >> 2);
    int gate = wid & 3;
    int row = gate * HID + u;

    const float4* w = (const float4*)(w_ih + (size_t)row * HID);
    const float4* x4 = (const float4*)(layer ? g_hl0 : g_x);
    float s = warp_reduce(row_dot_1k(w, x4, lane));
    if (lane == 0)
        s_g[wid] = s + g_hh[layer * 4 * HID + row] + b_ih[row] + b_hh[row];
    __syncthreads();

    if (t < 2) {
        int u2 = blockIdx.x * 2 + t;
        int b = t * 4;
        float gi = s_g[b + 0], gf = s_g[b + 1], gg = s_g[b + 2], go = s_g[b + 3];
        float si = 1.f / (1.f + expf(-gi));
        float sf = 1.f / (1.f + expf(-gf));
        float so = 1.f / (1.f + expf(-go));
        float c2 = sf * cprev[u2] + si * tanhf(gg);
        float h2 = so * tanhf(c2);
        c_out[u2] = c2;
        h_out[u2] = h2;
        if (layer) g_hl1[u2] = h2; else g_hl0[u2] = h2;
    }
}

// ---------------------------------------------------------------------------
// K5: logits = h_l1 @ out_w.T + out_b (warp per row) + per-block lse partials
// ---------------------------------------------------------------------------
__global__ void __launch_bounds__(256)
k_logits(const float* __restrict__ out_w,
         const float* __restrict__ out_b,
         float* __restrict__ logits) {
    __shared__ float s_l[8];
    int t = threadIdx.x;
    int wid = t >> 5, lane = t & 31;
    int r = blockIdx.x * 8 + wid;

    if (r < VOC) {
        const float4* w = (const float4*)(out_w + (size_t)r * HID);
        const float4* h4 = (const float4*)g_hl1;
        float s = warp_reduce(row_dot_1k(w, h4, lane));
        if (lane == 0) {
            float lg = s + out_b[r];
            logits[r] = lg;
            s_l[wid] = lg;
        }
    } else if (lane == 0) {
        s_l[wid] = -INFINITY;
    }
    __syncthreads();

    if (t == 0) {
        float m = s_l[0];
#pragma unroll
        for (int k = 1; k < 8; k++) m = fmaxf(m, s_l[k]);
        float sum = 0.f;
#pragma unroll
        for (int k = 0; k < 8; k++) sum += expf(s_l[k] - m);
        g_pm[blockIdx.x] = m;
        g_ps[blockIdx.x] = sum;
    }
}

// ---------------------------------------------------------------------------
// K6: fused log-sum-exp + subtract. Every block redundantly reduces the 6283
// partials (L2-resident) and then normalizes its own slice of logits.
// ---------------------------------------------------------------------------
__global__ void __launch_bounds__(256)
k_finish(float* __restrict__ logits) {
    __shared__ float red[256];
    int t = threadIdx.x;
    float m = -INFINITY;
    for (int i = t; i < NPART; i += 256) m = fmaxf(m, g_pm[i]);
    red[t] = m;
    __syncthreads();
#pragma unroll
    for (int o = 128; o; o >>= 1) {
        if (t < o) red[t] = fmaxf(red[t], red[t + o]);
        __syncthreads();
    }
    m = red[0];
    __syncthreads();
    float s = 0.f;
    for (int i = t; i < NPART; i += 256) s += g_ps[i] * expf(g_pm[i] - m);
    red[t] = s;
    __syncthreads();
#pragma unroll
    for (int o = 128; o; o >>= 1) {
        if (t < o) red[t] += red[t + o];
        __syncthreads();
    }
    __syncthreads();
    float lse = m + logf(red[0]);

    int idx = blockIdx.x * 256 + t;
    if (idx < VOC) logits[idx] -= lse;
}

// ---------------------------------------------------------------------------
// Output layout: [log_probs(V) | h_new(2*H) | c_new(2*H) | attn_weights(L)]
// ---------------------------------------------------------------------------
extern "C" void kernel_launch(void* const* d_in, const int* in_sizes, int n_in,
                              void* d_out, int out_size) {
    const int*   tok    = (const int*)  d_in[0];
    const float* h0     = (const float*)d_in[1];
    const float* c0     = (const float*)d_in[2];
    const float* enc    = (const float*)d_in[3];
    const float* emb    = (const float*)d_in[4];
    const float* attn_w = (const float*)d_in[5];
    const float* attn_b = (const float*)d_in[6];
    const float* comb_w = (const float*)d_in[7];
    const float* comb_b = (const float*)d_in[8];
    const float* w_ih0  = (const float*)d_in[9];
    const float* w_hh0  = (const float*)d_in[10];
    const float* b_ih0  = (const float*)d_in[11];
    const float* b_hh0  = (const float*)d_in[12];
    const float* w_ih1  = (const float*)d_in[13];
    const float* w_hh1  = (const float*)d_in[14];
    const float* b_ih1  = (const float*)d_in[15];
    const float* b_hh1  = (const float*)d_in[16];
    const float* out_w  = (const float*)d_in[17];
    const float* out_b  = (const float*)d_in[18];

    float* out      = (float*)d_out;
    float* o_logp   = out;
    float* o_h      = out + VOC;
    float* o_c      = out + VOC + 2 * HID;
    float* o_attn   = out + VOC + 4 * HID;

    // one-time side stream + events for a parallel graph branch
    static cudaStream_t s_side = nullptr;
    static cudaEvent_t ev_fork = nullptr, ev_whh = nullptr;
    if (s_side == nullptr) {
        cudaStreamCreateWithFlags(&s_side, cudaStreamNonBlocking);
        cudaEventCreateWithFlags(&ev_fork, cudaEventDisableTiming);
        cudaEventCreateWithFlags(&ev_whh, cudaEventDisableTiming);
    }

    // fork: w_hh partials run concurrently with attn + comb
    cudaEventRecord(ev_fork, 0);
    cudaStreamWaitEvent(s_side, ev_fork, 0);
    k_whh<<<1024, 256, 0, s_side>>>(h0, w_hh0, w_hh1);
    cudaEventRecord(ev_whh, s_side);

    k_attn<<<1, 512>>>(tok, h0, emb, attn_w, attn_b, enc, o_attn);
    k_comb<<<128, 256>>>(comb_w, comb_b);

    // join: lstm needs g_hh
    cudaStreamWaitEvent(0, ev_whh, 0);
    k_lstm<<<512, 256>>>(0, c0,       w_ih0, b_ih0, b_hh0, o_h,       o_c);
    k_lstm<<<512, 256>>>(1, c0 + HID, w_ih1, b_ih1, b_hh1, o_h + HID, o_c + HID);
    k_logits<<<NPART, 256>>>(out_w, out_b, o_logp);
    k_finish<<<(VOC + 255) / 256, 256>>>(o_logp);
}

// round 10
// speedup vs baseline: 1.1056x; 1.0276x over previous
#include <cuda_runtime.h>
#include <math.h>

#define HID 1024
#define LEN 40
#define VOC 50257
#define NPART 3142   // ceil(VOC/16) logits blocks

// ---- scratch (no allocations allowed) ----
__device__ float g_concat[3 * HID];   // [embedded ; attn_applied]
__device__ float g_x[HID];            // relu(comb) output
__device__ float g_hl0[HID];          // layer-0 hidden out
__device__ float g_hl1[HID];          // layer-1 hidden out
__device__ float g_hh[8 * HID];       // w_hh·h_prev partials, both layers
__device__ float g_pm[NPART];         // per-block logit max
__device__ float g_ps[NPART];         // per-block expsum

__device__ __forceinline__ float warp_reduce(float s) {
#pragma unroll
    for (int o = 16; o; o >>= 1) s += __shfl_down_sync(0xFFFFFFFFu, s, o);
    return s;
}

__device__ __forceinline__ float dot4(float4 a, float4 b) {
    return a.x * b.x + a.y * b.y + a.z * b.z + a.w * b.w;
}

// Four consecutive streaming LDG.128 (stride 512 B) in one asm block:
// back-to-back issue, register-resident results.
__device__ __forceinline__ void ldg4x4(const float4* p,
                                       float4& a, float4& b, float4& c, float4& d) {
    asm volatile(
        "ld.global.cs.v4.f32 {%0,%1,%2,%3}, [%16];\n\t"
        "ld.global.cs.v4.f32 {%4,%5,%6,%7}, [%16+512];\n\t"
        "ld.global.cs.v4.f32 {%8,%9,%10,%11}, [%16+1024];\n\t"
        "ld.global.cs.v4.f32 {%12,%13,%14,%15}, [%16+1536];"
        : "=f"(a.x), "=f"(a.y), "=f"(a.z), "=f"(a.w),
          "=f"(b.x), "=f"(b.y), "=f"(b.z), "=f"(b.w),
          "=f"(c.x), "=f"(c.y), "=f"(c.z), "=f"(c.w),
          "=f"(d.x), "=f"(d.y), "=f"(d.z), "=f"(d.w)
        : "l"(p));
}

// TWO 1024-float rows dotted against the same vector. All 16 LDG.128 issue
// before any FMA => MLP=16 per warp. Vector chunk loaded once, used twice.
__device__ __forceinline__ void row2_dot_1k(const float4* wA, const float4* wB,
                                            const float4* v4, int lane,
                                            float& outA, float& outB) {
    float4 a0,a1,a2,a3,a4,a5,a6,a7;
    float4 b0,b1,b2,b3,b4,b5,b6,b7;
    ldg4x4(wA + lane,       a0, a1, a2, a3);
    ldg4x4(wA + lane + 128, a4, a5, a6, a7);
    ldg4x4(wB + lane,       b0, b1, b2, b3);
    ldg4x4(wB + lane + 128, b4, b5, b6, b7);
    float sA = 0.f, sB = 0.f;
    float4 v;
    v = v4[lane];       sA += dot4(v, a0); sB += dot4(v, b0);
    v = v4[lane + 32];  sA += dot4(v, a1); sB += dot4(v, b1);
    v = v4[lane + 64];  sA += dot4(v, a2); sB += dot4(v, b2);
    v = v4[lane + 96];  sA += dot4(v, a3); sB += dot4(v, b3);
    v = v4[lane + 128]; sA += dot4(v, a4); sB += dot4(v, b4);
    v = v4[lane + 160]; sA += dot4(v, a5); sB += dot4(v, b5);
    v = v4[lane + 192]; sA += dot4(v, a6); sB += dot4(v, b6);
    v = v4[lane + 224]; sA += dot4(v, a7); sB += dot4(v, b7);
    outA += sA; outB += sB;
}

// ---------------------------------------------------------------------------
// K0 (side branch): w_hh partials, BOTH layers. Warp per ROW-PAIR.
// 8192 rows -> 4096 warp tasks -> 512 blocks x 256.
// ---------------------------------------------------------------------------
__global__ void __launch_bounds__(256, 2)
k_whh(const float* __restrict__ h0,
      const float* __restrict__ w_hh0,
      const float* __restrict__ w_hh1) {
    int t = threadIdx.x;
    int wid = t >> 5, lane = t & 31;
    int p = blockIdx.x * 8 + wid;                // 0..4095 row pairs
    int r0 = p * 2;                              // even: pair in same layer
    int layer = r0 >> 12;
    int row = r0 & 4095;
    const float* w_hh = layer ? w_hh1 : w_hh0;
    const float4* wA = (const float4*)(w_hh + (size_t)row * HID);
    const float4* wB = (const float4*)(w_hh + (size_t)(row + 1) * HID);
    const float4* h4 = (const float4*)(h0 + layer * HID);
    float sA = 0.f, sB = 0.f;
    row2_dot_1k(wA, wB, h4, lane, sA, sB);
    sA = warp_reduce(sA);
    sB = warp_reduce(sB);
    if (lane == 0) { g_hh[r0] = sA; g_hh[r0 + 1] = sB; }
}

// ---------------------------------------------------------------------------
// K1: embedding gather + attention logits + softmax + context (one block)
// ---------------------------------------------------------------------------
__global__ void __launch_bounds__(512)
k_attn(const int* __restrict__ tok,
       const float* __restrict__ h0,
       const float* __restrict__ emb,
       const float* __restrict__ attn_w,
       const float* __restrict__ attn_b,
       const float* __restrict__ enc,
       float* __restrict__ out_attnw) {
    __shared__ float s_ain[3 * HID];
    __shared__ float s_log[LEN];
    __shared__ float s_w[LEN];
    int t = threadIdx.x;            // 512 threads
    int token = tok[0];
    for (int i = t; i < HID; i += 512) {
        s_ain[i]           = emb[(size_t)token * HID + i];
        s_ain[HID + i]     = h0[i];
        s_ain[2 * HID + i] = h0[HID + i];
    }
    __syncthreads();

    int warp = t >> 5, lane = t & 31;   // 16 warps
    for (int l = warp; l < LEN; l += 16) {
        const float4* w = (const float4*)(attn_w + (size_t)l * 3 * HID);
        const float4* a = (const float4*)s_ain;
        float s = 0.f;
#pragma unroll
        for (int c = 0; c < 3; c++) {
            float4 w0, w1, w2, w3, w4, w5, w6, w7;
            const float4* base = w + lane + 256 * c;
            ldg4x4(base,       w0, w1, w2, w3);
            ldg4x4(base + 128, w4, w5, w6, w7);
            int i0 = lane + 256 * c;
            s += dot4(a[i0],       w0) + dot4(a[i0 + 32],  w1)
               + dot4(a[i0 + 64],  w2) + dot4(a[i0 + 96],  w3)
               + dot4(a[i0 + 128], w4) + dot4(a[i0 + 160], w5)
               + dot4(a[i0 + 192], w6) + dot4(a[i0 + 224], w7);
        }
        s = warp_reduce(s);
        if (lane == 0) s_log[l] = s + attn_b[l];
    }
    __syncthreads();

    if (t == 0) {
        float m = s_log[0];
        for (int l = 1; l < LEN; l++) m = fmaxf(m, s_log[l]);
        float sum = 0.f;
        for (int l = 0; l < LEN; l++) { float e = expf(s_log[l] - m); s_w[l] = e; sum += e; }
        float inv = 1.f / sum;
        for (int l = 0; l < LEN; l++) { s_w[l] *= inv; out_attnw[l] = s_w[l]; }
    }
    __syncthreads();

    for (int j = t; j < 2 * HID; j += 512) {
        float s = 0.f;
#pragma unroll
        for (int l = 0; l < LEN; l++) s += s_w[l] * enc[l * 2 * HID + j];
        g_concat[HID + j] = s;
    }
    for (int i = t; i < HID; i += 512) g_concat[i] = s_ain[i];
}

// ---------------------------------------------------------------------------
// K2: x = relu([emb;attn] @ comb_w.T + comb_b). Warp per ROW-PAIR.
// 1024 rows -> 512 warps -> 64 blocks x 256. Rows are 3072 long (3 chunks).
// ---------------------------------------------------------------------------
__global__ void __launch_bounds__(256, 2)
k_comb(const float* __restrict__ comb_w,
       const float* __restrict__ comb_b) {
    int t = threadIdx.x;
    int wid = t >> 5, lane = t & 31;
    int r0 = (blockIdx.x * 8 + wid) * 2;         // even row of pair
    const float4* wA = (const float4*)(comb_w + (size_t)r0 * 3 * HID);
    const float4* wB = (const float4*)(comb_w + (size_t)(r0 + 1) * 3 * HID);
    const float4* v = (const float4*)g_concat;
    float sA = 0.f, sB = 0.f;
#pragma unroll
    for (int c = 0; c < 3; c++)
        row2_dot_1k(wA + 256 * c, wB + 256 * c, v + 256 * c, lane, sA, sB);
    sA = warp_reduce(sA);
    sB = warp_reduce(sB);
    if (lane == 0) {
        g_x[r0]     = fmaxf(sA + comb_b[r0], 0.f);
        g_x[r0 + 1] = fmaxf(sB + comb_b[r0 + 1], 0.f);
    }
}

// ---------------------------------------------------------------------------
// K3: LSTM w_ih matvec + combine (w_hh precomputed in g_hh).
// Block = 4 units. Warp w: gate = w&3, unit pair = w>>2.
// 256 blocks x 256 thr per layer.
// ---------------------------------------------------------------------------
__global__ void __launch_bounds__(256, 2)
k_lstm(int layer,
       const float* __restrict__ cprev,
       const float* __restrict__ w_ih,
       const float* __restrict__ b_ih,
       const float* __restrict__ b_hh,
       float* __restrict__ h_out,
       float* __restrict__ c_out) {
    __shared__ float s_g[4][4];                  // [gate][local unit]
    int t = threadIdx.x;
    int wid = t >> 5, lane = t & 31;
    int gate = wid & 3;
    int upair = wid >> 2;                        // 0..1
    int u0 = blockIdx.x * 4 + upair * 2;         // first unit of this warp
    int r0 = gate * HID + u0;

    const float4* wA = (const float4*)(w_ih + (size_t)r0 * HID);
    const float4* wB = (const float4*)(w_ih + (size_t)(r0 + 1) * HID);
    const float4* x4 = (const float4*)(layer ? g_hl0 : g_x);
    float sA = 0.f, sB = 0.f;
    row2_dot_1k(wA, wB, x4, lane, sA, sB);
    sA = warp_reduce(sA);
    sB = warp_reduce(sB);
    if (lane == 0) {
        int base = layer * 4 * HID;
        s_g[gate][upair * 2]     = sA + g_hh[base + r0]     + b_ih[r0]     + b_hh[r0];
        s_g[gate][upair * 2 + 1] = sB + g_hh[base + r0 + 1] + b_ih[r0 + 1] + b_hh[r0 + 1];
    }
    __syncthreads();

    if (t < 4) {
        int u = blockIdx.x * 4 + t;
        float gi = s_g[0][t], gf = s_g[1][t], gg = s_g[2][t], go = s_g[3][t];
        float si = 1.f / (1.f + expf(-gi));
        float sf = 1.f / (1.f + expf(-gf));
        float so = 1.f / (1.f + expf(-go));
        float c2 = sf * cprev[u] + si * tanhf(gg);
        float h2 = so * tanhf(c2);
        c_out[u] = c2;
        h_out[u] = h2;
        if (layer) g_hl1[u] = h2; else g_hl0[u] = h2;
    }
}

// ---------------------------------------------------------------------------
// K5: logits (warp per ROW-PAIR, 16 rows/block) + per-block lse partials
// ---------------------------------------------------------------------------
__global__ void __launch_bounds__(256, 2)
k_logits(const float* __restrict__ out_w,
         const float* __restrict__ out_b,
         float* __restrict__ logits) {
    __shared__ float s_l[16];
    int t = threadIdx.x;
    int wid = t >> 5, lane = t & 31;
    int r0 = blockIdx.x * 16 + wid * 2;

    const float4* h4 = (const float4*)g_hl1;
    if (r0 + 1 < VOC) {
        const float4* wA = (const float4*)(out_w + (size_t)r0 * HID);
        const float4* wB = (const float4*)(out_w + (size_t)(r0 + 1) * HID);
        float sA = 0.f, sB = 0.f;
        row2_dot_1k(wA, wB, h4, lane, sA, sB);
        sA = warp_reduce(sA);
        sB = warp_reduce(sB);
        if (lane == 0) {
            float lgA = sA + out_b[r0];
            float lgB = sB + out_b[r0 + 1];
            logits[r0] = lgA;
            logits[r0 + 1] = lgB;
            s_l[wid * 2] = lgA;
            s_l[wid * 2 + 1] = lgB;
        }
    } else if (r0 < VOC) {        // single tail row
        const float4* wA = (const float4*)(out_w + (size_t)r0 * HID);
        float4 w0, w1, w2, w3, w4, w5, w6, w7;
        ldg4x4(wA + lane,       w0, w1, w2, w3);
        ldg4x4(wA + lane + 128, w4, w5, w6, w7);
        float s = dot4(h4[lane],       w0) + dot4(h4[lane + 32],  w1)
                + dot4(h4[lane + 64],  w2) + dot4(h4[lane + 96],  w3)
                + dot4(h4[lane + 128], w4) + dot4(h4[lane + 160], w5)
                + dot4(h4[lane + 192], w6) + dot4(h4[lane + 224], w7);
        s = warp_reduce(s);
        if (lane == 0) {
            float lg = s + out_b[r0];
            logits[r0] = lg;
            s_l[wid * 2] = lg;
            s_l[wid * 2 + 1] = -INFINITY;
        }
    } else if (lane == 0) {
        s_l[wid * 2] = -INFINITY;
        s_l[wid * 2 + 1] = -INFINITY;
    }
    __syncthreads();

    if (t == 0) {
        float m = s_l[0];
#pragma unroll
        for (int k = 1; k < 16; k++) m = fmaxf(m, s_l[k]);
        float sum = 0.f;
#pragma unroll
        for (int k = 0; k < 16; k++) sum += expf(s_l[k] - m);
        g_pm[blockIdx.x] = m;
        g_ps[blockIdx.x] = sum;
    }
}

// ---------------------------------------------------------------------------
// K6: fused log-sum-exp + subtract. Every block redundantly reduces the
// NPART partials (L2-resident) and normalizes its own slice of logits.
// ---------------------------------------------------------------------------
__global__ void __launch_bounds__(256)
k_finish(float* __restrict__ logits) {
    __shared__ float red[256];
    int t = threadIdx.x;
    float m = -INFINITY;
    for (int i = t; i < NPART; i += 256) m = fmaxf(m, g_pm[i]);
    red[t] = m;
    __syncthreads();
#pragma unroll
    for (int o = 128; o; o >>= 1) {
        if (t < o) red[t] = fmaxf(red[t], red[t + o]);
        __syncthreads();
    }
    m = red[0];
    __syncthreads();
    float s = 0.f;
    for (int i = t; i < NPART; i += 256) s += g_ps[i] * expf(g_pm[i] - m);
    red[t] = s;
    __syncthreads();
#pragma unroll
    for (int o = 128; o; o >>= 1) {
        if (t < o) red[t] += red[t + o];
        __syncthreads();
    }
    __syncthreads();
    float lse = m + logf(red[0]);

    int idx = blockIdx.x * 256 + t;
    if (idx < VOC) logits[idx] -= lse;
}

// ---------------------------------------------------------------------------
// Output layout: [log_probs(V) | h_new(2*H) | c_new(2*H) | attn_weights(L)]
// ---------------------------------------------------------------------------
extern "C" void kernel_launch(void* const* d_in, const int* in_sizes, int n_in,
                              void* d_out, int out_size) {
    const int*   tok    = (const int*)  d_in[0];
    const float* h0     = (const float*)d_in[1];
    const float* c0     = (const float*)d_in[2];
    const float* enc    = (const float*)d_in[3];
    const float* emb    = (const float*)d_in[4];
    const float* attn_w = (const float*)d_in[5];
    const float* attn_b = (const float*)d_in[6];
    const float* comb_w = (const float*)d_in[7];
    const float* comb_b = (const float*)d_in[8];
    const float* w_ih0  = (const float*)d_in[9];
    const float* w_hh0  = (const float*)d_in[10];
    const float* b_ih0  = (const float*)d_in[11];
    const float* b_hh0  = (const float*)d_in[12];
    const float* w_ih1  = (const float*)d_in[13];
    const float* w_hh1  = (const float*)d_in[14];
    const float* b_ih1  = (const float*)d_in[15];
    const float* b_hh1  = (const float*)d_in[16];
    const float* out_w  = (const float*)d_in[17];
    const float* out_b  = (const float*)d_in[18];

    float* out      = (float*)d_out;
    float* o_logp   = out;
    float* o_h      = out + VOC;
    float* o_c      = out + VOC + 2 * HID;
    float* o_attn   = out + VOC + 4 * HID;

    // one-time side stream + events for a parallel graph branch
    static cudaStream_t s_side = nullptr;
    static cudaEvent_t ev_fork = nullptr, ev_whh = nullptr;
    if (s_side == nullptr) {
        cudaStreamCreateWithFlags(&s_side, cudaStreamNonBlocking);
        cudaEventCreateWithFlags(&ev_fork, cudaEventDisableTiming);
        cudaEventCreateWithFlags(&ev_whh, cudaEventDisableTiming);
    }

    // fork: w_hh partials run concurrently with attn + comb
    cudaEventRecord(ev_fork, 0);
    cudaStreamWaitEvent(s_side, ev_fork, 0);
    k_whh<<<512, 256, 0, s_side>>>(h0, w_hh0, w_hh1);
    cudaEventRecord(ev_whh, s_side);

    k_attn<<<1, 512>>>(tok, h0, emb, attn_w, attn_b, enc, o_attn);
    k_comb<<<64, 256>>>(comb_w, comb_b);

    // join: lstm needs g_hh
    cudaStreamWaitEvent(0, ev_whh, 0);
    k_lstm<<<256, 256>>>(0, c0,       w_ih0, b_ih0, b_hh0, o_h,       o_c);
    k_lstm<<<256, 256>>>(1, c0 + HID, w_ih1, b_ih1, b_hh1, o_h + HID, o_c + HID);
    k_logits<<<NPART, 256>>>(out_w, out_b, o_logp);
    k_finish<<<(VOC + 255) / 256, 256>>>(o_logp);
}

// round 11
// speedup vs baseline: 1.2422x; 1.1236x over previous
#include <cuda_runtime.h>
#include <math.h>

#define HID 1024
#define LEN 40
#define VOC 50257
#define NPART 3142   // ceil(VOC/16) logits blocks

// ---- scratch (no allocations allowed) ----
__device__ float g_concat[3 * HID];   // [embedded ; attn_applied]
__device__ float g_x[HID];            // relu(comb) output
__device__ float g_hl0[HID];          // layer-0 hidden out
__device__ float g_hl1[HID];          // layer-1 hidden out
__device__ float g_pm[NPART];         // per-block logit max
__device__ float g_ps[NPART];         // per-block expsum

#define GDC_LAUNCH() asm volatile("griddepcontrol.launch_dependents;")
#define GDC_WAIT()   asm volatile("griddepcontrol.wait;" ::: "memory")

__device__ __forceinline__ float warp_reduce(float s) {
#pragma unroll
    for (int o = 16; o; o >>= 1) s += __shfl_down_sync(0xFFFFFFFFu, s, o);
    return s;
}

__device__ __forceinline__ float dot4(float4 a, float4 b) {
    return a.x * b.x + a.y * b.y + a.z * b.z + a.w * b.w;
}

// Four consecutive streaming LDG.128 (stride 512 B) in one asm block:
// back-to-back issue, register-resident results.
__device__ __forceinline__ void ldg4x4(const float4* p,
                                       float4& a, float4& b, float4& c, float4& d) {
    asm volatile(
        "ld.global.cs.v4.f32 {%0,%1,%2,%3}, [%16];\n\t"
        "ld.global.cs.v4.f32 {%4,%5,%6,%7}, [%16+512];\n\t"
        "ld.global.cs.v4.f32 {%8,%9,%10,%11}, [%16+1024];\n\t"
        "ld.global.cs.v4.f32 {%12,%13,%14,%15}, [%16+1536];"
        : "=f"(a.x), "=f"(a.y), "=f"(a.z), "=f"(a.w),
          "=f"(b.x), "=f"(b.y), "=f"(b.z), "=f"(b.w),
          "=f"(c.x), "=f"(c.y), "=f"(c.z), "=f"(c.w),
          "=f"(d.x), "=f"(d.y), "=f"(d.z), "=f"(d.w)
        : "l"(p));
}

// TWO 1024-float rows dotted against the same vector; 16 LDG in flight.
__device__ __forceinline__ void row2_dot_1k(const float4* wA, const float4* wB,
                                            const float4* v4, int lane,
                                            float& outA, float& outB) {
    float4 a0,a1,a2,a3,a4,a5,a6,a7;
    float4 b0,b1,b2,b3,b4,b5,b6,b7;
    ldg4x4(wA + lane,       a0, a1, a2, a3);
    ldg4x4(wA + lane + 128, a4, a5, a6, a7);
    ldg4x4(wB + lane,       b0, b1, b2, b3);
    ldg4x4(wB + lane + 128, b4, b5, b6, b7);
    float sA = 0.f, sB = 0.f;
    float4 v;
    v = v4[lane];       sA += dot4(v, a0); sB += dot4(v, b0);
    v = v4[lane + 32];  sA += dot4(v, a1); sB += dot4(v, b1);
    v = v4[lane + 64];  sA += dot4(v, a2); sB += dot4(v, b2);
    v = v4[lane + 96];  sA += dot4(v, a3); sB += dot4(v, b3);
    v = v4[lane + 128]; sA += dot4(v, a4); sB += dot4(v, b4);
    v = v4[lane + 160]; sA += dot4(v, a5); sB += dot4(v, b5);
    v = v4[lane + 192]; sA += dot4(v, a6); sB += dot4(v, b6);
    v = v4[lane + 224]; sA += dot4(v, a7); sB += dot4(v, b7);
    outA += sA; outB += sB;
}

// ---------------------------------------------------------------------------
// K1: embedding gather + attention logits + softmax + context (one block)
// ---------------------------------------------------------------------------
__global__ void __launch_bounds__(512)
k_attn(const int* __restrict__ tok,
       const float* __restrict__ h0,
       const float* __restrict__ emb,
       const float* __restrict__ attn_w,
       const float* __restrict__ attn_b,
       const float* __restrict__ enc,
       float* __restrict__ out_attnw) {
    GDC_LAUNCH();     // let comb launch + prefetch immediately (we're 1 block)
    __shared__ float s_ain[3 * HID];
    __shared__ float s_log[LEN];
    __shared__ float s_w[LEN];
    int t = threadIdx.x;            // 512 threads
    int token = tok[0];
    for (int i = t; i < HID; i += 512) {
        s_ain[i]           = emb[(size_t)token * HID + i];
        s_ain[HID + i]     = h0[i];
        s_ain[2 * HID + i] = h0[HID + i];
    }
    __syncthreads();

    int warp = t >> 5, lane = t & 31;   // 16 warps
    for (int l = warp; l < LEN; l += 16) {
        const float4* w = (const float4*)(attn_w + (size_t)l * 3 * HID);
        const float4* a = (const float4*)s_ain;
        float s = 0.f;
#pragma unroll
        for (int c = 0; c < 3; c++) {
            float4 w0, w1, w2, w3, w4, w5, w6, w7;
            const float4* base = w + lane + 256 * c;
            ldg4x4(base,       w0, w1, w2, w3);
            ldg4x4(base + 128, w4, w5, w6, w7);
            int i0 = lane + 256 * c;
            s += dot4(a[i0],       w0) + dot4(a[i0 + 32],  w1)
               + dot4(a[i0 + 64],  w2) + dot4(a[i0 + 96],  w3)
               + dot4(a[i0 + 128], w4) + dot4(a[i0 + 160], w5)
               + dot4(a[i0 + 192], w6) + dot4(a[i0 + 224], w7);
        }
        s = warp_reduce(s);
        if (lane == 0) s_log[l] = s + attn_b[l];
    }
    __syncthreads();

    if (t == 0) {
        float m = s_log[0];
        for (int l = 1; l < LEN; l++) m = fmaxf(m, s_log[l]);
        float sum = 0.f;
        for (int l = 0; l < LEN; l++) { float e = expf(s_log[l] - m); s_w[l] = e; sum += e; }
        float inv = 1.f / sum;
        for (int l = 0; l < LEN; l++) { s_w[l] *= inv; out_attnw[l] = s_w[l]; }
    }
    __syncthreads();

    for (int j = t; j < 2 * HID; j += 512) {
        float s = 0.f;
#pragma unroll
        for (int l = 0; l < LEN; l++) s += s_w[l] * enc[l * 2 * HID + j];
        g_concat[HID + j] = s;
    }
    for (int i = t; i < HID; i += 512) g_concat[i] = s_ain[i];
}

// ---------------------------------------------------------------------------
// K2: x = relu([emb;attn] @ comb_w.T + comb_b). Warp per ROW-PAIR.
// Chunk-0 weights prefetched BEFORE the dependency wait.
// ---------------------------------------------------------------------------
__global__ void __launch_bounds__(256, 2)
k_comb(const float* __restrict__ comb_w,
       const float* __restrict__ comb_b) {
    int t = threadIdx.x;
    int wid = t >> 5, lane = t & 31;
    int r0 = (blockIdx.x * 8 + wid) * 2;         // even row of pair
    const float4* wA = (const float4*)(comb_w + (size_t)r0 * 3 * HID);
    const float4* wB = (const float4*)(comb_w + (size_t)(r0 + 1) * 3 * HID);

    // prefetch chunk 0 (independent of parent)
    float4 a0,a1,a2,a3,a4,a5,a6,a7, b0,b1,b2,b3,b4,b5,b6,b7;
    ldg4x4(wA + lane,       a0, a1, a2, a3);
    ldg4x4(wA + lane + 128, a4, a5, a6, a7);
    ldg4x4(wB + lane,       b0, b1, b2, b3);
    ldg4x4(wB + lane + 128, b4, b5, b6, b7);
    GDC_LAUNCH();
    GDC_WAIT();                                   // g_concat ready

    const float4* v = (const float4*)g_concat;
    float sA = 0.f, sB = 0.f;
    float4 vv;
    vv = v[lane];       sA += dot4(vv, a0); sB += dot4(vv, b0);
    vv = v[lane + 32];  sA += dot4(vv, a1); sB += dot4(vv, b1);
    vv = v[lane + 64];  sA += dot4(vv, a2); sB += dot4(vv, b2);
    vv = v[lane + 96];  sA += dot4(vv, a3); sB += dot4(vv, b3);
    vv = v[lane + 128]; sA += dot4(vv, a4); sB += dot4(vv, b4);
    vv = v[lane + 160]; sA += dot4(vv, a5); sB += dot4(vv, b5);
    vv = v[lane + 192]; sA += dot4(vv, a6); sB += dot4(vv, b6);
    vv = v[lane + 224]; sA += dot4(vv, a7); sB += dot4(vv, b7);
#pragma unroll
    for (int c = 1; c < 3; c++)
        row2_dot_1k(wA + 256 * c, wB + 256 * c, v + 256 * c, lane, sA, sB);
    sA = warp_reduce(sA);
    sB = warp_reduce(sB);
    if (lane == 0) {
        g_x[r0]     = fmaxf(sA + comb_b[r0], 0.f);
        g_x[r0 + 1] = fmaxf(sB + comb_b[r0 + 1], 0.f);
    }
}

// ---------------------------------------------------------------------------
// K3: full LSTM cell with PDL: pre-wait = w_hh·h_prev (inputs only) + w_ih
// prefetch; post-wait = x dot + gate math. Block = 4 units.
// ---------------------------------------------------------------------------
__global__ void __launch_bounds__(256, 2)
k_lstm(int layer,
       const float* __restrict__ hprev,
       const float* __restrict__ cprev,
       const float* __restrict__ w_ih,
       const float* __restrict__ w_hh,
       const float* __restrict__ b_ih,
       const float* __restrict__ b_hh,
       float* __restrict__ h_out,
       float* __restrict__ c_out) {
    __shared__ float s_g[4][4];                  // [gate][local unit]
    int t = threadIdx.x;
    int wid = t >> 5, lane = t & 31;
    int gate = wid & 3;
    int upair = wid >> 2;                        // 0..1
    int u0 = blockIdx.x * 4 + upair * 2;
    int r0 = gate * HID + u0;

    // --- pre-wait phase: everything that only needs kernel inputs ---
    const float4* whA = (const float4*)(w_hh + (size_t)r0 * HID);
    const float4* whB = (const float4*)(w_hh + (size_t)(r0 + 1) * HID);
    const float4* h4  = (const float4*)hprev;
    float sA = 0.f, sB = 0.f;
    row2_dot_1k(whA, whB, h4, lane, sA, sB);     // 16 MB stream, input-only

    const float4* wiA = (const float4*)(w_ih + (size_t)r0 * HID);
    const float4* wiB = (const float4*)(w_ih + (size_t)(r0 + 1) * HID);
    float4 a0,a1,a2,a3,a4,a5,a6,a7, b0,b1,b2,b3,b4,b5,b6,b7;
    ldg4x4(wiA + lane,       a0, a1, a2, a3);
    ldg4x4(wiA + lane + 128, a4, a5, a6, a7);
    ldg4x4(wiB + lane,       b0, b1, b2, b3);
    ldg4x4(wiB + lane + 128, b4, b5, b6, b7);
    GDC_LAUNCH();
    GDC_WAIT();                                   // x (g_x / g_hl0) ready

    const float4* x4 = (const float4*)(layer ? g_hl0 : g_x);
    float4 v;
    v = x4[lane];       sA += dot4(v, a0); sB += dot4(v, b0);
    v = x4[lane + 32];  sA += dot4(v, a1); sB += dot4(v, b1);
    v = x4[lane + 64];  sA += dot4(v, a2); sB += dot4(v, b2);
    v = x4[lane + 96];  sA += dot4(v, a3); sB += dot4(v, b3);
    v = x4[lane + 128]; sA += dot4(v, a4); sB += dot4(v, b4);
    v = x4[lane + 160]; sA += dot4(v, a5); sB += dot4(v, b5);
    v = x4[lane + 192]; sA += dot4(v, a6); sB += dot4(v, b6);
    v = x4[lane + 224]; sA += dot4(v, a7); sB += dot4(v, b7);
    sA = warp_reduce(sA);
    sB = warp_reduce(sB);
    if (lane == 0) {
        s_g[gate][upair * 2]     = sA + b_ih[r0]     + b_hh[r0];
        s_g[gate][upair * 2 + 1] = sB + b_ih[r0 + 1] + b_hh[r0 + 1];
    }
    __syncthreads();

    if (t < 4) {
        int u = blockIdx.x * 4 + t;
        float gi = s_g[0][t], gf = s_g[1][t], gg = s_g[2][t], go = s_g[3][t];
        float si = 1.f / (1.f + expf(-gi));
        float sf = 1.f / (1.f + expf(-gf));
        float so = 1.f / (1.f + expf(-go));
        float c2 = sf * cprev[u] + si * tanhf(gg);
        float h2 = so * tanhf(c2);
        c_out[u] = c2;
        h_out[u] = h2;
        if (layer) g_hl1[u] = h2; else g_hl0[u] = h2;
    }
}

// ---------------------------------------------------------------------------
// K5: logits (warp per ROW-PAIR) + per-block lse partials.
// Weights prefetched pre-wait; first resident wave overlaps lstm1.
// ---------------------------------------------------------------------------
__global__ void __launch_bounds__(256, 2)
k_logits(const float* __restrict__ out_w,
         const float* __restrict__ out_b,
         float* __restrict__ logits) {
    __shared__ float s_l[16];
    int t = threadIdx.x;
    int wid = t >> 5, lane = t & 31;
    int r0 = blockIdx.x * 16 + wid * 2;
    bool pair = (r0 + 1 < VOC);
    bool single = (!pair) && (r0 < VOC);

    float4 a0,a1,a2,a3,a4,a5,a6,a7, b0,b1,b2,b3,b4,b5,b6,b7;
    if (pair) {
        const float4* wA = (const float4*)(out_w + (size_t)r0 * HID);
        const float4* wB = (const float4*)(out_w + (size_t)(r0 + 1) * HID);
        ldg4x4(wA + lane,       a0, a1, a2, a3);
        ldg4x4(wA + lane + 128, a4, a5, a6, a7);
        ldg4x4(wB + lane,       b0, b1, b2, b3);
        ldg4x4(wB + lane + 128, b4, b5, b6, b7);
    } else if (single) {
        const float4* wA = (const float4*)(out_w + (size_t)r0 * HID);
        ldg4x4(wA + lane,       a0, a1, a2, a3);
        ldg4x4(wA + lane + 128, a4, a5, a6, a7);
    }
    GDC_LAUNCH();
    GDC_WAIT();                                   // g_hl1 ready

    const float4* h4 = (const float4*)g_hl1;
    if (pair) {
        float sA = 0.f, sB = 0.f;
        float4 v;
        v = h4[lane];       sA += dot4(v, a0); sB += dot4(v, b0);
        v = h4[lane + 32];  sA += dot4(v, a1); sB += dot4(v, b1);
        v = h4[lane + 64];  sA += dot4(v, a2); sB += dot4(v, b2);
        v = h4[lane + 96];  sA += dot4(v, a3); sB += dot4(v, b3);
        v = h4[lane + 128]; sA += dot4(v, a4); sB += dot4(v, b4);
        v = h4[lane + 160]; sA += dot4(v, a5); sB += dot4(v, b5);
        v = h4[lane + 192]; sA += dot4(v, a6); sB += dot4(v, b6);
        v = h4[lane + 224]; sA += dot4(v, a7); sB += dot4(v, b7);
        sA = warp_reduce(sA);
        sB = warp_reduce(sB);
        if (lane == 0) {
            float lgA = sA + out_b[r0];
            float lgB = sB + out_b[r0 + 1];
            logits[r0] = lgA;
            logits[r0 + 1] = lgB;
            s_l[wid * 2] = lgA;
            s_l[wid * 2 + 1] = lgB;
        }
    } else if (single) {
        float s = dot4(h4[lane],       a0) + dot4(h4[lane + 32],  a1)
                + dot4(h4[lane + 64],  a2) + dot4(h4[lane + 96],  a3)
                + dot4(h4[lane + 128], a4) + dot4(h4[lane + 160], a5)
                + dot4(h4[lane + 192], a6) + dot4(h4[lane + 224], a7);
        s = warp_reduce(s);
        if (lane == 0) {
            float lg = s + out_b[r0];
            logits[r0] = lg;
            s_l[wid * 2] = lg;
            s_l[wid * 2 + 1] = -INFINITY;
        }
    } else if (lane == 0) {
        s_l[wid * 2] = -INFINITY;
        s_l[wid * 2 + 1] = -INFINITY;
    }
    __syncthreads();

    if (t == 0) {
        float m = s_l[0];
#pragma unroll
        for (int k = 1; k < 16; k++) m = fmaxf(m, s_l[k]);
        float sum = 0.f;
#pragma unroll
        for (int k = 0; k < 16; k++) sum += expf(s_l[k] - m);
        g_pm[blockIdx.x] = m;
        g_ps[blockIdx.x] = sum;
    }
}

// ---------------------------------------------------------------------------
// K6: fused log-sum-exp + subtract.
// ---------------------------------------------------------------------------
__global__ void __launch_bounds__(256)
k_finish(float* __restrict__ logits) {
    GDC_WAIT();
    __shared__ float red[256];
    int t = threadIdx.x;
    float m = -INFINITY;
    for (int i = t; i < NPART; i += 256) m = fmaxf(m, g_pm[i]);
    red[t] = m;
    __syncthreads();
#pragma unroll
    for (int o = 128; o; o >>= 1) {
        if (t < o) red[t] = fmaxf(red[t], red[t + o]);
        __syncthreads();
    }
    m = red[0];
    __syncthreads();
    float s = 0.f;
    for (int i = t; i < NPART; i += 256) s += g_ps[i] * expf(g_pm[i] - m);
    red[t] = s;
    __syncthreads();
#pragma unroll
    for (int o = 128; o; o >>= 1) {
        if (t < o) red[t] += red[t + o];
        __syncthreads();
    }
    __syncthreads();
    float lse = m + logf(red[0]);

    int idx = blockIdx.x * 256 + t;
    if (idx < VOC) logits[idx] -= lse;
}

// ---------------------------------------------------------------------------
// host: PDL launch helper
// ---------------------------------------------------------------------------
static void launch_pdl(const void* fn, dim3 grid, dim3 block, void** args) {
    cudaLaunchConfig_t cfg = {};
    cfg.gridDim = grid;
    cfg.blockDim = block;
    cfg.dynamicSmemBytes = 0;
    cfg.stream = 0;
    cudaLaunchAttribute at[1];
    at[0].id = cudaLaunchAttributeProgrammaticStreamSerialization;
    at[0].val.programmaticStreamSerializationAllowed = 1;
    cfg.attrs = at;
    cfg.numAttrs = 1;
    cudaLaunchKernelExC(&cfg, fn, args);
}

// ---------------------------------------------------------------------------
// Output layout: [log_probs(V) | h_new(2*H) | c_new(2*H) | attn_weights(L)]
// ---------------------------------------------------------------------------
extern "C" void kernel_launch(void* const* d_in, const int* in_sizes, int n_in,
                              void* d_out, int out_size) {
    const int*   tok    = (const int*)  d_in[0];
    const float* h0     = (const float*)d_in[1];
    const float* c0     = (const float*)d_in[2];
    const float* enc    = (const float*)d_in[3];
    const float* emb    = (const float*)d_in[4];
    const float* attn_w = (const float*)d_in[5];
    const float* attn_b = (const float*)d_in[6];
    const float* comb_w = (const float*)d_in[7];
    const float* comb_b = (const float*)d_in[8];
    const float* w_ih0  = (const float*)d_in[9];
    const float* w_hh0  = (const float*)d_in[10];
    const float* b_ih0  = (const float*)d_in[11];
    const float* b_hh0  = (const float*)d_in[12];
    const float* w_ih1  = (const float*)d_in[13];
    const float* w_hh1  = (const float*)d_in[14];
    const float* b_ih1  = (const float*)d_in[15];
    const float* b_hh1  = (const float*)d_in[16];
    const float* out_w  = (const float*)d_in[17];
    const float* out_b  = (const float*)d_in[18];

    float* out      = (float*)d_out;
    float* o_logp   = out;
    float* o_h      = out + VOC;
    float* o_c      = out + VOC + 2 * HID;
    float* o_attn   = out + VOC + 4 * HID;

    k_attn<<<1, 512>>>(tok, h0, emb, attn_w, attn_b, enc, o_attn);

    {
        void* args[] = {(void*)&comb_w, (void*)&comb_b};
        launch_pdl((const void*)k_comb, dim3(64), dim3(256), args);
    }
    {
        int layer = 0;
        const float* hp = h0;
        const float* cp = c0;
        float* ho = o_h;
        float* co = o_c;
        void* args[] = {&layer, (void*)&hp, (void*)&cp,
                        (void*)&w_ih0, (void*)&w_hh0,
                        (void*)&b_ih0, (void*)&b_hh0, &ho, &co};
        launch_pdl((const void*)k_lstm, dim3(256), dim3(256), args);
    }
    {
        int layer = 1;
        const float* hp = h0 + HID;
        const float* cp = c0 + HID;
        float* ho = o_h + HID;
        float* co = o_c + HID;
        void* args[] = {&layer, (void*)&hp, (void*)&cp,
                        (void*)&w_ih1, (void*)&w_hh1,
                        (void*)&b_ih1, (void*)&b_hh1, &ho, &co};
        launch_pdl((const void*)k_lstm, dim3(256), dim3(256), args);
    }
    {
        void* args[] = {(void*)&out_w, (void*)&out_b, (void*)&o_logp};
        launch_pdl((const void*)k_logits, dim3(NPART), dim3(256), args);
    }
    {
        void* args[] = {(void*)&o_logp};
        launch_pdl((const void*)k_finish, dim3((VOC + 255) / 256), dim3(256), args);
    }
}

// round 12
// speedup vs baseline: 1.2428x; 1.0005x over previous
#include <cuda_runtime.h>
#include <math.h>

#define HID 1024
#define LEN 40
#define VOC 50257
#define NPART 3142   // ceil(VOC/16) logits blocks

// ---- scratch (no allocations allowed) ----
__device__ float g_concat[3 * HID];   // [embedded ; attn_applied]
__device__ float g_x[HID];            // relu(comb) output
__device__ float g_hl0[HID];          // layer-0 hidden out
__device__ float g_hl1[HID];          // layer-1 hidden out
__device__ float g_hh1[4 * HID];      // w_hh1·h0[1] partials (layer 1)
__device__ float g_pm[NPART];         // per-block logit max
__device__ float g_ps[NPART];         // per-block expsum

#define GDC_LAUNCH() asm volatile("griddepcontrol.launch_dependents;")
#define GDC_WAIT()   asm volatile("griddepcontrol.wait;" ::: "memory")

__device__ __forceinline__ float warp_reduce(float s) {
#pragma unroll
    for (int o = 16; o; o >>= 1) s += __shfl_down_sync(0xFFFFFFFFu, s, o);
    return s;
}

__device__ __forceinline__ float dot4(float4 a, float4 b) {
    return a.x * b.x + a.y * b.y + a.z * b.z + a.w * b.w;
}

// Four consecutive streaming LDG.128 (stride 512 B) in one asm block.
__device__ __forceinline__ void ldg4x4(const float4* p,
                                       float4& a, float4& b, float4& c, float4& d) {
    asm volatile(
        "ld.global.cs.v4.f32 {%0,%1,%2,%3}, [%16];\n\t"
        "ld.global.cs.v4.f32 {%4,%5,%6,%7}, [%16+512];\n\t"
        "ld.global.cs.v4.f32 {%8,%9,%10,%11}, [%16+1024];\n\t"
        "ld.global.cs.v4.f32 {%12,%13,%14,%15}, [%16+1536];"
        : "=f"(a.x), "=f"(a.y), "=f"(a.z), "=f"(a.w),
          "=f"(b.x), "=f"(b.y), "=f"(b.z), "=f"(b.w),
          "=f"(c.x), "=f"(c.y), "=f"(c.z), "=f"(c.w),
          "=f"(d.x), "=f"(d.y), "=f"(d.z), "=f"(d.w)
        : "l"(p));
}

// TWO 1024-float rows dotted against the same vector; 16 LDG in flight.
__device__ __forceinline__ void row2_dot_1k(const float4* wA, const float4* wB,
                                            const float4* v4, int lane,
                                            float& outA, float& outB) {
    float4 a0,a1,a2,a3,a4,a5,a6,a7;
    float4 b0,b1,b2,b3,b4,b5,b6,b7;
    ldg4x4(wA + lane,       a0, a1, a2, a3);
    ldg4x4(wA + lane + 128, a4, a5, a6, a7);
    ldg4x4(wB + lane,       b0, b1, b2, b3);
    ldg4x4(wB + lane + 128, b4, b5, b6, b7);
    float sA = 0.f, sB = 0.f;
    float4 v;
    v = v4[lane];       sA += dot4(v, a0); sB += dot4(v, b0);
    v = v4[lane + 32];  sA += dot4(v, a1); sB += dot4(v, b1);
    v = v4[lane + 64];  sA += dot4(v, a2); sB += dot4(v, b2);
    v = v4[lane + 96];  sA += dot4(v, a3); sB += dot4(v, b3);
    v = v4[lane + 128]; sA += dot4(v, a4); sB += dot4(v, b4);
    v = v4[lane + 160]; sA += dot4(v, a5); sB += dot4(v, b5);
    v = v4[lane + 192]; sA += dot4(v, a6); sB += dot4(v, b6);
    v = v4[lane + 224]; sA += dot4(v, a7); sB += dot4(v, b7);
    outA += sA; outB += sB;
}

// ---------------------------------------------------------------------------
// K1: embedding gather + attention logits + softmax + context (one block)
// ---------------------------------------------------------------------------
__global__ void __launch_bounds__(512)
k_attn(const int* __restrict__ tok,
       const float* __restrict__ h0,
       const float* __restrict__ emb,
       const float* __restrict__ attn_w,
       const float* __restrict__ attn_b,
       const float* __restrict__ enc,
       float* __restrict__ out_attnw) {
    GDC_LAUNCH();     // let successors launch + prefetch immediately
    __shared__ float s_ain[3 * HID];
    __shared__ float s_log[LEN];
    __shared__ float s_w[LEN];
    int t = threadIdx.x;            // 512 threads
    int token = tok[0];
    for (int i = t; i < HID; i += 512) {
        s_ain[i]           = emb[(size_t)token * HID + i];
        s_ain[HID + i]     = h0[i];
        s_ain[2 * HID + i] = h0[HID + i];
    }
    __syncthreads();

    int warp = t >> 5, lane = t & 31;   // 16 warps
    for (int l = warp; l < LEN; l += 16) {
        const float4* w = (const float4*)(attn_w + (size_t)l * 3 * HID);
        const float4* a = (const float4*)s_ain;
        float s = 0.f;
#pragma unroll
        for (int c = 0; c < 3; c++) {
            float4 w0, w1, w2, w3, w4, w5, w6, w7;
            const float4* base = w + lane + 256 * c;
            ldg4x4(base,       w0, w1, w2, w3);
            ldg4x4(base + 128, w4, w5, w6, w7);
            int i0 = lane + 256 * c;
            s += dot4(a[i0],       w0) + dot4(a[i0 + 32],  w1)
               + dot4(a[i0 + 64],  w2) + dot4(a[i0 + 96],  w3)
               + dot4(a[i0 + 128], w4) + dot4(a[i0 + 160], w5)
               + dot4(a[i0 + 192], w6) + dot4(a[i0 + 224], w7);
        }
        s = warp_reduce(s);
        if (lane == 0) s_log[l] = s + attn_b[l];
    }
    __syncthreads();

    if (t == 0) {
        float m = s_log[0];
        for (int l = 1; l < LEN; l++) m = fmaxf(m, s_log[l]);
        float sum = 0.f;
        for (int l = 0; l < LEN; l++) { float e = expf(s_log[l] - m); s_w[l] = e; sum += e; }
        float inv = 1.f / sum;
        for (int l = 0; l < LEN; l++) { s_w[l] *= inv; out_attnw[l] = s_w[l]; }
    }
    __syncthreads();

    for (int j = t; j < 2 * HID; j += 512) {
        float s = 0.f;
#pragma unroll
        for (int l = 0; l < LEN; l++) s += s_w[l] * enc[l * 2 * HID + j];
        g_concat[HID + j] = s;
    }
    for (int i = t; i < HID; i += 512) g_concat[i] = s_ain[i];
}

// ---------------------------------------------------------------------------
// K2: x = relu([emb;attn] @ comb_w.T + comb_b). Warp per ROW-PAIR.
// Chunk-0 weights prefetched BEFORE the dependency wait.
// ---------------------------------------------------------------------------
__global__ void __launch_bounds__(256, 2)
k_comb(const float* __restrict__ comb_w,
       const float* __restrict__ comb_b) {
    int t = threadIdx.x;
    int wid = t >> 5, lane = t & 31;
    int r0 = (blockIdx.x * 8 + wid) * 2;         // even row of pair
    const float4* wA = (const float4*)(comb_w + (size_t)r0 * 3 * HID);
    const float4* wB = (const float4*)(comb_w + (size_t)(r0 + 1) * 3 * HID);

    // prefetch chunk 0 (independent of parent)
    float4 a0,a1,a2,a3,a4,a5,a6,a7, b0,b1,b2,b3,b4,b5,b6,b7;
    ldg4x4(wA + lane,       a0, a1, a2, a3);
    ldg4x4(wA + lane + 128, a4, a5, a6, a7);
    ldg4x4(wB + lane,       b0, b1, b2, b3);
    ldg4x4(wB + lane + 128, b4, b5, b6, b7);
    GDC_LAUNCH();
    GDC_WAIT();                                   // g_concat ready

    const float4* v = (const float4*)g_concat;
    float sA = 0.f, sB = 0.f;
    float4 vv;
    vv = v[lane];       sA += dot4(vv, a0); sB += dot4(vv, b0);
    vv = v[lane + 32];  sA += dot4(vv, a1); sB += dot4(vv, b1);
    vv = v[lane + 64];  sA += dot4(vv, a2); sB += dot4(vv, b2);
    vv = v[lane + 96];  sA += dot4(vv, a3); sB += dot4(vv, b3);
    vv = v[lane + 128]; sA += dot4(vv, a4); sB += dot4(vv, b4);
    vv = v[lane + 160]; sA += dot4(vv, a5); sB += dot4(vv, b5);
    vv = v[lane + 192]; sA += dot4(vv, a6); sB += dot4(vv, b6);
    vv = v[lane + 224]; sA += dot4(vv, a7); sB += dot4(vv, b7);
#pragma unroll
    for (int c = 1; c < 3; c++)
        row2_dot_1k(wA + 256 * c, wB + 256 * c, v + 256 * c, lane, sA, sB);
    sA = warp_reduce(sA);
    sB = warp_reduce(sB);
    if (lane == 0) {
        g_x[r0]     = fmaxf(sA + comb_b[r0], 0.f);
        g_x[r0 + 1] = fmaxf(sB + comb_b[r0 + 1], 0.f);
    }
}

// ---------------------------------------------------------------------------
// K3a: blocks [0,256): layer-1 w_hh partials (INPUT-ONLY, no wait — streams
//      during attn/comb). blocks [256,512): full lstm layer-0 cell with PDL.
// ---------------------------------------------------------------------------
__global__ void __launch_bounds__(256, 2)
k_lstm_a(const float* __restrict__ h0,
         const float* __restrict__ c0,
         const float* __restrict__ w_ih0,
         const float* __restrict__ w_hh0,
         const float* __restrict__ w_hh1,
         const float* __restrict__ b_ih0,
         const float* __restrict__ b_hh0,
         float* __restrict__ h_out,
         float* __restrict__ c_out) {
    int bid = blockIdx.x;
    int t = threadIdx.x;
    int wid = t >> 5, lane = t & 31;

    if (bid < 256) {
        // ---- layer-1 w_hh partials: 4096 rows, 2 rows/warp ----
        GDC_LAUNCH();
        int r0 = (bid * 8 + wid) * 2;            // 0..4094 (row within layer)
        const float4* wA = (const float4*)(w_hh1 + (size_t)r0 * HID);
        const float4* wB = (const float4*)(w_hh1 + (size_t)(r0 + 1) * HID);
        const float4* h4 = (const float4*)(h0 + HID);
        float sA = 0.f, sB = 0.f;
        row2_dot_1k(wA, wB, h4, lane, sA, sB);
        sA = warp_reduce(sA);
        sB = warp_reduce(sB);
        if (lane == 0) { g_hh1[r0] = sA; g_hh1[r0 + 1] = sB; }
        return;
    }

    // ---- lstm layer 0: 4 units/block ----
    __shared__ float s_g[4][4];                  // [gate][local unit]
    int gate = wid & 3;
    int upair = wid >> 2;                        // 0..1
    int u0 = (bid - 256) * 4 + upair * 2;
    int r0 = gate * HID + u0;

    // pre-wait: w_hh0·h0 (inputs only) + w_ih0 prefetch
    const float4* whA = (const float4*)(w_hh0 + (size_t)r0 * HID);
    const float4* whB = (const float4*)(w_hh0 + (size_t)(r0 + 1) * HID);
    const float4* h4  = (const float4*)h0;
    float sA = 0.f, sB = 0.f;
    row2_dot_1k(whA, whB, h4, lane, sA, sB);

    const float4* wiA = (const float4*)(w_ih0 + (size_t)r0 * HID);
    const float4* wiB = (const float4*)(w_ih0 + (size_t)(r0 + 1) * HID);
    float4 a0,a1,a2,a3,a4,a5,a6,a7, b0,b1,b2,b3,b4,b5,b6,b7;
    ldg4x4(wiA + lane,       a0, a1, a2, a3);
    ldg4x4(wiA + lane + 128, a4, a5, a6, a7);
    ldg4x4(wiB + lane,       b0, b1, b2, b3);
    ldg4x4(wiB + lane + 128, b4, b5, b6, b7);
    GDC_LAUNCH();
    GDC_WAIT();                                   // g_x ready

    const float4* x4 = (const float4*)g_x;
    float4 v;
    v = x4[lane];       sA += dot4(v, a0); sB += dot4(v, b0);
    v = x4[lane + 32];  sA += dot4(v, a1); sB += dot4(v, b1);
    v = x4[lane + 64];  sA += dot4(v, a2); sB += dot4(v, b2);
    v = x4[lane + 96];  sA += dot4(v, a3); sB += dot4(v, b3);
    v = x4[lane + 128]; sA += dot4(v, a4); sB += dot4(v, b4);
    v = x4[lane + 160]; sA += dot4(v, a5); sB += dot4(v, b5);
    v = x4[lane + 192]; sA += dot4(v, a6); sB += dot4(v, b6);
    v = x4[lane + 224]; sA += dot4(v, a7); sB += dot4(v, b7);
    sA = warp_reduce(sA);
    sB = warp_reduce(sB);
    if (lane == 0) {
        s_g[gate][upair * 2]     = sA + b_ih0[r0]     + b_hh0[r0];
        s_g[gate][upair * 2 + 1] = sB + b_ih0[r0 + 1] + b_hh0[r0 + 1];
    }
    __syncthreads();

    if (t < 4) {
        int u = (bid - 256) * 4 + t;
        float gi = s_g[0][t], gf = s_g[1][t], gg = s_g[2][t], go = s_g[3][t];
        float si = 1.f / (1.f + expf(-gi));
        float sf = 1.f / (1.f + expf(-gf));
        float so = 1.f / (1.f + expf(-go));
        float c2 = sf * c0[u] + si * tanhf(gg);
        float h2 = so * tanhf(c2);
        c_out[u] = c2;
        h_out[u] = h2;
        g_hl0[u] = h2;
    }
}

// ---------------------------------------------------------------------------
// K3b: lstm layer 1 — w_ih1 only (w_hh1 part precomputed into g_hh1).
// All 16 weight loads prefetched pre-wait; post-wait is L1 x-dots + gates.
// ---------------------------------------------------------------------------
__global__ void __launch_bounds__(256, 2)
k_lstm_b(const float* __restrict__ h0,
         const float* __restrict__ c0,
         const float* __restrict__ w_ih1,
         const float* __restrict__ b_ih1,
         const float* __restrict__ b_hh1,
         float* __restrict__ h_out,
         float* __restrict__ c_out) {
    __shared__ float s_g[4][4];
    int t = threadIdx.x;
    int wid = t >> 5, lane = t & 31;
    int gate = wid & 3;
    int upair = wid >> 2;
    int u0 = blockIdx.x * 4 + upair * 2;
    int r0 = gate * HID + u0;

    const float4* wiA = (const float4*)(w_ih1 + (size_t)r0 * HID);
    const float4* wiB = (const float4*)(w_ih1 + (size_t)(r0 + 1) * HID);
    float4 a0,a1,a2,a3,a4,a5,a6,a7, b0,b1,b2,b3,b4,b5,b6,b7;
    ldg4x4(wiA + lane,       a0, a1, a2, a3);
    ldg4x4(wiA + lane + 128, a4, a5, a6, a7);
    ldg4x4(wiB + lane,       b0, b1, b2, b3);
    ldg4x4(wiB + lane + 128, b4, b5, b6, b7);
    GDC_LAUNCH();
    GDC_WAIT();                                   // g_hl0 + g_hh1 ready

    const float4* x4 = (const float4*)g_hl0;
    float sA = 0.f, sB = 0.f;
    float4 v;
    v = x4[lane];       sA += dot4(v, a0); sB += dot4(v, b0);
    v = x4[lane + 32];  sA += dot4(v, a1); sB += dot4(v, b1);
    v = x4[lane + 64];  sA += dot4(v, a2); sB += dot4(v, b2);
    v = x4[lane + 96];  sA += dot4(v, a3); sB += dot4(v, b3);
    v = x4[lane + 128]; sA += dot4(v, a4); sB += dot4(v, b4);
    v = x4[lane + 160]; sA += dot4(v, a5); sB += dot4(v, b5);
    v = x4[lane + 192]; sA += dot4(v, a6); sB += dot4(v, b6);
    v = x4[lane + 224]; sA += dot4(v, a7); sB += dot4(v, b7);
    sA = warp_reduce(sA);
    sB = warp_reduce(sB);
    if (lane == 0) {
        s_g[gate][upair * 2]     = sA + g_hh1[r0]     + b_ih1[r0]     + b_hh1[r0];
        s_g[gate][upair * 2 + 1] = sB + g_hh1[r0 + 1] + b_ih1[r0 + 1] + b_hh1[r0 + 1];
    }
    __syncthreads();

    if (t < 4) {
        int u = blockIdx.x * 4 + t;
        float gi = s_g[0][t], gf = s_g[1][t], gg = s_g[2][t], go = s_g[3][t];
        float si = 1.f / (1.f + expf(-gi));
        float sf = 1.f / (1.f + expf(-gf));
        float so = 1.f / (1.f + expf(-go));
        float c2 = sf * c0[HID + u] + si * tanhf(gg);
        float h2 = so * tanhf(c2);
        c_out[u] = c2;
        h_out[u] = h2;
        g_hl1[u] = h2;
    }
}

// ---------------------------------------------------------------------------
// K5: logits (warp per ROW-PAIR) + per-block lse partials.
// ---------------------------------------------------------------------------
__global__ void __launch_bounds__(256, 2)
k_logits(const float* __restrict__ out_w,
         const float* __restrict__ out_b,
         float* __restrict__ logits) {
    __shared__ float s_l[16];
    int t = threadIdx.x;
    int wid = t >> 5, lane = t & 31;
    int r0 = blockIdx.x * 16 + wid * 2;
    bool pair = (r0 + 1 < VOC);
    bool single = (!pair) && (r0 < VOC);

    float4 a0,a1,a2,a3,a4,a5,a6,a7, b0,b1,b2,b3,b4,b5,b6,b7;
    if (pair) {
        const float4* wA = (const float4*)(out_w + (size_t)r0 * HID);
        const float4* wB = (const float4*)(out_w + (size_t)(r0 + 1) * HID);
        ldg4x4(wA + lane,       a0, a1, a2, a3);
        ldg4x4(wA + lane + 128, a4, a5, a6, a7);
        ldg4x4(wB + lane,       b0, b1, b2, b3);
        ldg4x4(wB + lane + 128, b4, b5, b6, b7);
    } else if (single) {
        const float4* wA = (const float4*)(out_w + (size_t)r0 * HID);
        ldg4x4(wA + lane,       a0, a1, a2, a3);
        ldg4x4(wA + lane + 128, a4, a5, a6, a7);
    }
    GDC_LAUNCH();
    GDC_WAIT();                                   // g_hl1 ready

    const float4* h4 = (const float4*)g_hl1;
    if (pair) {
        float sA = 0.f, sB = 0.f;
        float4 v;
        v = h4[lane];       sA += dot4(v, a0); sB += dot4(v, b0);
        v = h4[lane + 32];  sA += dot4(v, a1); sB += dot4(v, b1);
        v = h4[lane + 64];  sA += dot4(v, a2); sB += dot4(v, b2);
        v = h4[lane + 96];  sA += dot4(v, a3); sB += dot4(v, b3);
        v = h4[lane + 128]; sA += dot4(v, a4); sB += dot4(v, b4);
        v = h4[lane + 160]; sA += dot4(v, a5); sB += dot4(v, b5);
        v = h4[lane + 192]; sA += dot4(v, a6); sB += dot4(v, b6);
        v = h4[lane + 224]; sA += dot4(v, a7); sB += dot4(v, b7);
        sA = warp_reduce(sA);
        sB = warp_reduce(sB);
        if (lane == 0) {
            float lgA = sA + out_b[r0];
            float lgB = sB + out_b[r0 + 1];
            logits[r0] = lgA;
            logits[r0 + 1] = lgB;
            s_l[wid * 2] = lgA;
            s_l[wid * 2 + 1] = lgB;
        }
    } else if (single) {
        float s = dot4(h4[lane],       a0) + dot4(h4[lane + 32],  a1)
                + dot4(h4[lane + 64],  a2) + dot4(h4[lane + 96],  a3)
                + dot4(h4[lane + 128], a4) + dot4(h4[lane + 160], a5)
                + dot4(h4[lane + 192], a6) + dot4(h4[lane + 224], a7);
        s = warp_reduce(s);
        if (lane == 0) {
            float lg = s + out_b[r0];
            logits[r0] = lg;
            s_l[wid * 2] = lg;
            s_l[wid * 2 + 1] = -INFINITY;
        }
    } else if (lane == 0) {
        s_l[wid * 2] = -INFINITY;
        s_l[wid * 2 + 1] = -INFINITY;
    }
    __syncthreads();

    if (t == 0) {
        float m = s_l[0];
#pragma unroll
        for (int k = 1; k < 16; k++) m = fmaxf(m, s_l[k]);
        float sum = 0.f;
#pragma unroll
        for (int k = 0; k < 16; k++) sum += expf(s_l[k] - m);
        g_pm[blockIdx.x] = m;
        g_ps[blockIdx.x] = sum;
    }
}

// ---------------------------------------------------------------------------
// K6: fused log-sum-exp + subtract.
// ---------------------------------------------------------------------------
__global__ void __launch_bounds__(256)
k_finish(float* __restrict__ logits) {
    GDC_WAIT();
    __shared__ float red[256];
    int t = threadIdx.x;
    float m = -INFINITY;
    for (int i = t; i < NPART; i += 256) m = fmaxf(m, g_pm[i]);
    red[t] = m;
    __syncthreads();
#pragma unroll
    for (int o = 128; o; o >>= 1) {
        if (t < o) red[t] = fmaxf(red[t], red[t + o]);
        __syncthreads();
    }
    m = red[0];
    __syncthreads();
    float s = 0.f;
    for (int i = t; i < NPART; i += 256) s += g_ps[i] * expf(g_pm[i] - m);
    red[t] = s;
    __syncthreads();
#pragma unroll
    for (int o = 128; o; o >>= 1) {
        if (t < o) red[t] += red[t + o];
        __syncthreads();
    }
    __syncthreads();
    float lse = m + logf(red[0]);

    int idx = blockIdx.x * 256 + t;
    if (idx < VOC) logits[idx] -= lse;
}

// ---------------------------------------------------------------------------
// host: PDL launch helper
// ---------------------------------------------------------------------------
static void launch_pdl(const void* fn, dim3 grid, dim3 block, void** args) {
    cudaLaunchConfig_t cfg = {};
    cfg.gridDim = grid;
    cfg.blockDim = block;
    cfg.dynamicSmemBytes = 0;
    cfg.stream = 0;
    cudaLaunchAttribute at[1];
    at[0].id = cudaLaunchAttributeProgrammaticStreamSerialization;
    at[0].val.programmaticStreamSerializationAllowed = 1;
    cfg.attrs = at;
    cfg.numAttrs = 1;
    cudaLaunchKernelExC(&cfg, fn, args);
}

// ---------------------------------------------------------------------------
// Output layout: [log_probs(V) | h_new(2*H) | c_new(2*H) | attn_weights(L)]
// ---------------------------------------------------------------------------
extern "C" void kernel_launch(void* const* d_in, const int* in_sizes, int n_in,
                              void* d_out, int out_size) {
    const int*   tok    = (const int*)  d_in[0];
    const float* h0     = (const float*)d_in[1];
    const float* c0     = (const float*)d_in[2];
    const float* enc    = (const float*)d_in[3];
    const float* emb    = (const float*)d_in[4];
    const float* attn_w = (const float*)d_in[5];
    const float* attn_b = (const float*)d_in[6];
    const float* comb_w = (const float*)d_in[7];
    const float* comb_b = (const float*)d_in[8];
    const float* w_ih0  = (const float*)d_in[9];
    const float* w_hh0  = (const float*)d_in[10];
    const float* b_ih0  = (const float*)d_in[11];
    const float* b_hh0  = (const float*)d_in[12];
    const float* w_ih1  = (const float*)d_in[13];
    const float* w_hh1  = (const float*)d_in[14];
    const float* b_ih1  = (const float*)d_in[15];
    const float* b_hh1  = (const float*)d_in[16];
    const float* out_w  = (const float*)d_in[17];
    const float* out_b  = (const float*)d_in[18];

    float* out      = (float*)d_out;
    float* o_logp   = out;
    float* o_h      = out + VOC;
    float* o_c      = out + VOC + 2 * HID;
    float* o_attn   = out + VOC + 4 * HID;

    k_attn<<<1, 512>>>(tok, h0, emb, attn_w, attn_b, enc, o_attn);

    {
        void* args[] = {(void*)&comb_w, (void*)&comb_b};
        launch_pdl((const void*)k_comb, dim3(64), dim3(256), args);
    }
    {
        float* ho = o_h;
        float* co = o_c;
        void* args[] = {(void*)&h0, (void*)&c0, (void*)&w_ih0, (void*)&w_hh0,
                        (void*)&w_hh1, (void*)&b_ih0, (void*)&b_hh0, &ho, &co};
        launch_pdl((const void*)k_lstm_a, dim3(512), dim3(256), args);
    }
    {
        float* ho = o_h + HID;
        float* co = o_c + HID;
        void* args[] = {(void*)&h0, (void*)&c0, (void*)&w_ih1,
                        (void*)&b_ih1, (void*)&b_hh1, &ho, &co};
        launch_pdl((const void*)k_lstm_b, dim3(256), dim3(256), args);
    }
    {
        void* args[] = {(void*)&out_w, (void*)&out_b, (void*)&o_logp};
        launch_pdl((const void*)k_logits, dim3(NPART), dim3(256), args);
    }
    {
        void* args[] = {(void*)&o_logp};
        launch_pdl((const void*)k_finish, dim3((VOC + 255) / 256), dim3(256), args);
    }
}

// round 13
// speedup vs baseline: 1.2754x; 1.0262x over previous
#include <cuda_runtime.h>
#include <math.h>

#define HID 1024
#define LEN 40
#define VOC 50257
#define NPART 3142   // ceil(VOC/16) logits blocks

// ---- scratch (no allocations allowed) ----
__device__ float g_concat[3 * HID];   // [embedded ; attn_applied]
__device__ float g_x[HID];            // relu(comb) output
__device__ float g_hl0[HID];          // layer-0 hidden out
__device__ float g_hl1[HID];          // layer-1 hidden out
__device__ float g_hh1[4 * HID];      // w_hh1·h0[1] partials (layer 1)
__device__ float g_pm[NPART];         // per-block logit max
__device__ float g_ps[NPART];         // per-block expsum

#define GDC_LAUNCH() asm volatile("griddepcontrol.launch_dependents;")
#define GDC_WAIT()   asm volatile("griddepcontrol.wait;" ::: "memory")

__device__ __forceinline__ float warp_reduce(float s) {
#pragma unroll
    for (int o = 16; o; o >>= 1) s += __shfl_down_sync(0xFFFFFFFFu, s, o);
    return s;
}

__device__ __forceinline__ float dot4(float4 a, float4 b) {
    return a.x * b.x + a.y * b.y + a.z * b.z + a.w * b.w;
}

// Four consecutive streaming LDG.128 (stride 512 B) in one asm block.
__device__ __forceinline__ void ldg4x4(const float4* p,
                                       float4& a, float4& b, float4& c, float4& d) {
    asm volatile(
        "ld.global.cs.v4.f32 {%0,%1,%2,%3}, [%16];\n\t"
        "ld.global.cs.v4.f32 {%4,%5,%6,%7}, [%16+512];\n\t"
        "ld.global.cs.v4.f32 {%8,%9,%10,%11}, [%16+1024];\n\t"
        "ld.global.cs.v4.f32 {%12,%13,%14,%15}, [%16+1536];"
        : "=f"(a.x), "=f"(a.y), "=f"(a.z), "=f"(a.w),
          "=f"(b.x), "=f"(b.y), "=f"(b.z), "=f"(b.w),
          "=f"(c.x), "=f"(c.y), "=f"(c.z), "=f"(c.w),
          "=f"(d.x), "=f"(d.y), "=f"(d.z), "=f"(d.w)
        : "l"(p));
}

// TWO 1024-float rows dotted against the same vector; 16 LDG in flight.
__device__ __forceinline__ void row2_dot_1k(const float4* wA, const float4* wB,
                                            const float4* v4, int lane,
                                            float& outA, float& outB) {
    float4 a0,a1,a2,a3,a4,a5,a6,a7;
    float4 b0,b1,b2,b3,b4,b5,b6,b7;
    ldg4x4(wA + lane,       a0, a1, a2, a3);
    ldg4x4(wA + lane + 128, a4, a5, a6, a7);
    ldg4x4(wB + lane,       b0, b1, b2, b3);
    ldg4x4(wB + lane + 128, b4, b5, b6, b7);
    float sA = 0.f, sB = 0.f;
    float4 v;
    v = v4[lane];       sA += dot4(v, a0); sB += dot4(v, b0);
    v = v4[lane + 32];  sA += dot4(v, a1); sB += dot4(v, b1);
    v = v4[lane + 64];  sA += dot4(v, a2); sB += dot4(v, b2);
    v = v4[lane + 96];  sA += dot4(v, a3); sB += dot4(v, b3);
    v = v4[lane + 128]; sA += dot4(v, a4); sB += dot4(v, b4);
    v = v4[lane + 160]; sA += dot4(v, a5); sB += dot4(v, b5);
    v = v4[lane + 192]; sA += dot4(v, a6); sB += dot4(v, b6);
    v = v4[lane + 224]; sA += dot4(v, a7); sB += dot4(v, b7);
    outA += sA; outB += sB;
}

// ---------------------------------------------------------------------------
// K1: embedding gather + attention logits + softmax + context (one block)
// ---------------------------------------------------------------------------
__global__ void __launch_bounds__(512)
k_attn(const int* __restrict__ tok,
       const float* __restrict__ h0,
       const float* __restrict__ emb,
       const float* __restrict__ attn_w,
       const float* __restrict__ attn_b,
       const float* __restrict__ enc,
       float* __restrict__ out_attnw) {
    GDC_LAUNCH();     // release successors at entry
    __shared__ float s_ain[3 * HID];
    __shared__ float s_log[LEN];
    __shared__ float s_w[LEN];
    int t = threadIdx.x;            // 512 threads
    int token = tok[0];
    for (int i = t; i < HID; i += 512) {
        s_ain[i]           = emb[(size_t)token * HID + i];
        s_ain[HID + i]     = h0[i];
        s_ain[2 * HID + i] = h0[HID + i];
    }
    __syncthreads();

    int warp = t >> 5, lane = t & 31;   // 16 warps
    for (int l = warp; l < LEN; l += 16) {
        const float4* w = (const float4*)(attn_w + (size_t)l * 3 * HID);
        const float4* a = (const float4*)s_ain;
        float s = 0.f;
#pragma unroll
        for (int c = 0; c < 3; c++) {
            float4 w0, w1, w2, w3, w4, w5, w6, w7;
            const float4* base = w + lane + 256 * c;
            ldg4x4(base,       w0, w1, w2, w3);
            ldg4x4(base + 128, w4, w5, w6, w7);
            int i0 = lane + 256 * c;
            s += dot4(a[i0],       w0) + dot4(a[i0 + 32],  w1)
               + dot4(a[i0 + 64],  w2) + dot4(a[i0 + 96],  w3)
               + dot4(a[i0 + 128], w4) + dot4(a[i0 + 160], w5)
               + dot4(a[i0 + 192], w6) + dot4(a[i0 + 224], w7);
        }
        s = warp_reduce(s);
        if (lane == 0) s_log[l] = s + attn_b[l];
    }
    __syncthreads();

    if (t == 0) {
        float m = s_log[0];
        for (int l = 1; l < LEN; l++) m = fmaxf(m, s_log[l]);
        float sum = 0.f;
        for (int l = 0; l < LEN; l++) { float e = expf(s_log[l] - m); s_w[l] = e; sum += e; }
        float inv = 1.f / sum;
        for (int l = 0; l < LEN; l++) { s_w[l] *= inv; out_attnw[l] = s_w[l]; }
    }
    __syncthreads();

    for (int j = t; j < 2 * HID; j += 512) {
        float s = 0.f;
#pragma unroll
        for (int l = 0; l < LEN; l++) s += s_w[l] * enc[l * 2 * HID + j];
        g_concat[HID + j] = s;
    }
    for (int i = t; i < HID; i += 512) g_concat[i] = s_ain[i];
}

// ---------------------------------------------------------------------------
// K2: x = relu([emb;attn] @ comb_w.T + comb_b). Warp per ROW-PAIR.
// 128 blocks x 128 thr (4 warps) -> 1024 rows, 2x SM coverage vs before.
// ---------------------------------------------------------------------------
__global__ void __launch_bounds__(128, 2)
k_comb(const float* __restrict__ comb_w,
       const float* __restrict__ comb_b) {
    GDC_LAUNCH();                                 // release lstm_a at entry
    int t = threadIdx.x;
    int wid = t >> 5, lane = t & 31;
    int r0 = (blockIdx.x * 4 + wid) * 2;          // even row of pair
    const float4* wA = (const float4*)(comb_w + (size_t)r0 * 3 * HID);
    const float4* wB = (const float4*)(comb_w + (size_t)(r0 + 1) * 3 * HID);

    // prefetch chunk 0 (independent of parent)
    float4 a0,a1,a2,a3,a4,a5,a6,a7, b0,b1,b2,b3,b4,b5,b6,b7;
    ldg4x4(wA + lane,       a0, a1, a2, a3);
    ldg4x4(wA + lane + 128, a4, a5, a6, a7);
    ldg4x4(wB + lane,       b0, b1, b2, b3);
    ldg4x4(wB + lane + 128, b4, b5, b6, b7);
    GDC_WAIT();                                   // g_concat ready

    const float4* v = (const float4*)g_concat;
    float sA = 0.f, sB = 0.f;
    float4 vv;
    vv = v[lane];       sA += dot4(vv, a0); sB += dot4(vv, b0);
    vv = v[lane + 32];  sA += dot4(vv, a1); sB += dot4(vv, b1);
    vv = v[lane + 64];  sA += dot4(vv, a2); sB += dot4(vv, b2);
    vv = v[lane + 96];  sA += dot4(vv, a3); sB += dot4(vv, b3);
    vv = v[lane + 128]; sA += dot4(vv, a4); sB += dot4(vv, b4);
    vv = v[lane + 160]; sA += dot4(vv, a5); sB += dot4(vv, b5);
    vv = v[lane + 192]; sA += dot4(vv, a6); sB += dot4(vv, b6);
    vv = v[lane + 224]; sA += dot4(vv, a7); sB += dot4(vv, b7);
#pragma unroll
    for (int c = 1; c < 3; c++)
        row2_dot_1k(wA + 256 * c, wB + 256 * c, v + 256 * c, lane, sA, sB);
    sA = warp_reduce(sA);
    sB = warp_reduce(sB);
    if (lane == 0) {
        g_x[r0]     = fmaxf(sA + comb_b[r0], 0.f);
        g_x[r0 + 1] = fmaxf(sB + comb_b[r0 + 1], 0.f);
    }
}

// ---------------------------------------------------------------------------
// K3a: blocks [0,256): layer-1 w_hh partials (INPUT-ONLY, no wait).
//      blocks [256,512): full lstm layer-0 cell with PDL.
// ---------------------------------------------------------------------------
__global__ void __launch_bounds__(256, 2)
k_lstm_a(const float* __restrict__ h0,
         const float* __restrict__ c0,
         const float* __restrict__ w_ih0,
         const float* __restrict__ w_hh0,
         const float* __restrict__ w_hh1,
         const float* __restrict__ b_ih0,
         const float* __restrict__ b_hh0,
         float* __restrict__ h_out,
         float* __restrict__ c_out) {
    GDC_LAUNCH();                                 // release lstm_b at entry
    int bid = blockIdx.x;
    int t = threadIdx.x;
    int wid = t >> 5, lane = t & 31;

    if (bid < 256) {
        // ---- layer-1 w_hh partials: 4096 rows, 2 rows/warp ----
        int r0 = (bid * 8 + wid) * 2;            // 0..4094 (row within layer)
        const float4* wA = (const float4*)(w_hh1 + (size_t)r0 * HID);
        const float4* wB = (const float4*)(w_hh1 + (size_t)(r0 + 1) * HID);
        const float4* h4 = (const float4*)(h0 + HID);
        float sA = 0.f, sB = 0.f;
        row2_dot_1k(wA, wB, h4, lane, sA, sB);
        sA = warp_reduce(sA);
        sB = warp_reduce(sB);
        if (lane == 0) { g_hh1[r0] = sA; g_hh1[r0 + 1] = sB; }
        return;
    }

    // ---- lstm layer 0: 4 units/block ----
    __shared__ float s_g[4][4];                  // [gate][local unit]
    int gate = wid & 3;
    int upair = wid >> 2;                        // 0..1
    int u0 = (bid - 256) * 4 + upair * 2;
    int r0 = gate * HID + u0;

    // pre-wait: w_hh0·h0 (inputs only) + w_ih0 prefetch
    const float4* whA = (const float4*)(w_hh0 + (size_t)r0 * HID);
    const float4* whB = (const float4*)(w_hh0 + (size_t)(r0 + 1) * HID);
    const float4* h4  = (const float4*)h0;
    float sA = 0.f, sB = 0.f;
    row2_dot_1k(whA, whB, h4, lane, sA, sB);

    const float4* wiA = (const float4*)(w_ih0 + (size_t)r0 * HID);
    const float4* wiB = (const float4*)(w_ih0 + (size_t)(r0 + 1) * HID);
    float4 a0,a1,a2,a3,a4,a5,a6,a7, b0,b1,b2,b3,b4,b5,b6,b7;
    ldg4x4(wiA + lane,       a0, a1, a2, a3);
    ldg4x4(wiA + lane + 128, a4, a5, a6, a7);
    ldg4x4(wiB + lane,       b0, b1, b2, b3);
    ldg4x4(wiB + lane + 128, b4, b5, b6, b7);
    GDC_WAIT();                                   // g_x ready

    const float4* x4 = (const float4*)g_x;
    float4 v;
    v = x4[lane];       sA += dot4(v, a0); sB += dot4(v, b0);
    v = x4[lane + 32];  sA += dot4(v, a1); sB += dot4(v, b1);
    v = x4[lane + 64];  sA += dot4(v, a2); sB += dot4(v, b2);
    v = x4[lane + 96];  sA += dot4(v, a3); sB += dot4(v, b3);
    v = x4[lane + 128]; sA += dot4(v, a4); sB += dot4(v, b4);
    v = x4[lane + 160]; sA += dot4(v, a5); sB += dot4(v, b5);
    v = x4[lane + 192]; sA += dot4(v, a6); sB += dot4(v, b6);
    v = x4[lane + 224]; sA += dot4(v, a7); sB += dot4(v, b7);
    sA = warp_reduce(sA);
    sB = warp_reduce(sB);
    if (lane == 0) {
        s_g[gate][upair * 2]     = sA + b_ih0[r0]     + b_hh0[r0];
        s_g[gate][upair * 2 + 1] = sB + b_ih0[r0 + 1] + b_hh0[r0 + 1];
    }
    __syncthreads();

    if (t < 4) {
        int u = (bid - 256) * 4 + t;
        float gi = s_g[0][t], gf = s_g[1][t], gg = s_g[2][t], go = s_g[3][t];
        float si = 1.f / (1.f + expf(-gi));
        float sf = 1.f / (1.f + expf(-gf));
        float so = 1.f / (1.f + expf(-go));
        float c2 = sf * c0[u] + si * tanhf(gg);
        float h2 = so * tanhf(c2);
        c_out[u] = c2;
        h_out[u] = h2;
        g_hl0[u] = h2;
    }
}

// ---------------------------------------------------------------------------
// K3b: lstm layer 1 — w_ih1 only (w_hh1 part precomputed into g_hh1).
// ---------------------------------------------------------------------------
__global__ void __launch_bounds__(256, 2)
k_lstm_b(const float* __restrict__ h0,
         const float* __restrict__ c0,
         const float* __restrict__ w_ih1,
         const float* __restrict__ b_ih1,
         const float* __restrict__ b_hh1,
         float* __restrict__ h_out,
         float* __restrict__ c_out) {
    GDC_LAUNCH();                                 // release logits at entry
    __shared__ float s_g[4][4];
    int t = threadIdx.x;
    int wid = t >> 5, lane = t & 31;
    int gate = wid & 3;
    int upair = wid >> 2;
    int u0 = blockIdx.x * 4 + upair * 2;
    int r0 = gate * HID + u0;

    const float4* wiA = (const float4*)(w_ih1 + (size_t)r0 * HID);
    const float4* wiB = (const float4*)(w_ih1 + (size_t)(r0 + 1) * HID);
    float4 a0,a1,a2,a3,a4,a5,a6,a7, b0,b1,b2,b3,b4,b5,b6,b7;
    ldg4x4(wiA + lane,       a0, a1, a2, a3);
    ldg4x4(wiA + lane + 128, a4, a5, a6, a7);
    ldg4x4(wiB + lane,       b0, b1, b2, b3);
    ldg4x4(wiB + lane + 128, b4, b5, b6, b7);
    GDC_WAIT();                                   // g_hl0 + g_hh1 ready

    const float4* x4 = (const float4*)g_hl0;
    float sA = 0.f, sB = 0.f;
    float4 v;
    v = x4[lane];       sA += dot4(v, a0); sB += dot4(v, b0);
    v = x4[lane + 32];  sA += dot4(v, a1); sB += dot4(v, b1);
    v = x4[lane + 64];  sA += dot4(v, a2); sB += dot4(v, b2);
    v = x4[lane + 96];  sA += dot4(v, a3); sB += dot4(v, b3);
    v = x4[lane + 128]; sA += dot4(v, a4); sB += dot4(v, b4);
    v = x4[lane + 160]; sA += dot4(v, a5); sB += dot4(v, b5);
    v = x4[lane + 192]; sA += dot4(v, a6); sB += dot4(v, b6);
    v = x4[lane + 224]; sA += dot4(v, a7); sB += dot4(v, b7);
    sA = warp_reduce(sA);
    sB = warp_reduce(sB);
    if (lane == 0) {
        s_g[gate][upair * 2]     = sA + g_hh1[r0]     + b_ih1[r0]     + b_hh1[r0];
        s_g[gate][upair * 2 + 1] = sB + g_hh1[r0 + 1] + b_ih1[r0 + 1] + b_hh1[r0 + 1];
    }
    __syncthreads();

    if (t < 4) {
        int u = blockIdx.x * 4 + t;
        float gi = s_g[0][t], gf = s_g[1][t], gg = s_g[2][t], go = s_g[3][t];
        float si = 1.f / (1.f + expf(-gi));
        float sf = 1.f / (1.f + expf(-gf));
        float so = 1.f / (1.f + expf(-go));
        float c2 = sf * c0[HID + u] + si * tanhf(gg);
        float h2 = so * tanhf(c2);
        c_out[u] = c2;
        h_out[u] = h2;
        g_hl1[u] = h2;
    }
}

// ---------------------------------------------------------------------------
// K5: logits (warp per ROW-PAIR) + per-block lse partials.
// ---------------------------------------------------------------------------
__global__ void __launch_bounds__(256, 2)
k_logits(const float* __restrict__ out_w,
         const float* __restrict__ out_b,
         float* __restrict__ logits) {
    GDC_LAUNCH();                                 // release finish at entry
    __shared__ float s_l[16];
    int t = threadIdx.x;
    int wid = t >> 5, lane = t & 31;
    int r0 = blockIdx.x * 16 + wid * 2;
    bool pair = (r0 + 1 < VOC);
    bool single = (!pair) && (r0 < VOC);

    float4 a0,a1,a2,a3,a4,a5,a6,a7, b0,b1,b2,b3,b4,b5,b6,b7;
    if (pair) {
        const float4* wA = (const float4*)(out_w + (size_t)r0 * HID);
        const float4* wB = (const float4*)(out_w + (size_t)(r0 + 1) * HID);
        ldg4x4(wA + lane,       a0, a1, a2, a3);
        ldg4x4(wA + lane + 128, a4, a5, a6, a7);
        ldg4x4(wB + lane,       b0, b1, b2, b3);
        ldg4x4(wB + lane + 128, b4, b5, b6, b7);
    } else if (single) {
        const float4* wA = (const float4*)(out_w + (size_t)r0 * HID);
        ldg4x4(wA + lane,       a0, a1, a2, a3);
        ldg4x4(wA + lane + 128, a4, a5, a6, a7);
    }
    GDC_WAIT();                                   // g_hl1 ready

    const float4* h4 = (const float4*)g_hl1;
    if (pair) {
        float sA = 0.f, sB = 0.f;
        float4 v;
        v = h4[lane];       sA += dot4(v, a0); sB += dot4(v, b0);
        v = h4[lane + 32];  sA += dot4(v, a1); sB += dot4(v, b1);
        v = h4[lane + 64];  sA += dot4(v, a2); sB += dot4(v, b2);
        v = h4[lane + 96];  sA += dot4(v, a3); sB += dot4(v, b3);
        v = h4[lane + 128]; sA += dot4(v, a4); sB += dot4(v, b4);
        v = h4[lane + 160]; sA += dot4(v, a5); sB += dot4(v, b5);
        v = h4[lane + 192]; sA += dot4(v, a6); sB += dot4(v, b6);
        v = h4[lane + 224]; sA += dot4(v, a7); sB += dot4(v, b7);
        sA = warp_reduce(sA);
        sB = warp_reduce(sB);
        if (lane == 0) {
            float lgA = sA + out_b[r0];
            float lgB = sB + out_b[r0 + 1];
            logits[r0] = lgA;
            logits[r0 + 1] = lgB;
            s_l[wid * 2] = lgA;
            s_l[wid * 2 + 1] = lgB;
        }
    } else if (single) {
        float s = dot4(h4[lane],       a0) + dot4(h4[lane + 32],  a1)
                + dot4(h4[lane + 64],  a2) + dot4(h4[lane + 96],  a3)
                + dot4(h4[lane + 128], a4) + dot4(h4[lane + 160], a5)
                + dot4(h4[lane + 192], a6) + dot4(h4[lane + 224], a7);
        s = warp_reduce(s);
        if (lane == 0) {
            float lg = s + out_b[r0];
            logits[r0] = lg;
            s_l[wid * 2] = lg;
            s_l[wid * 2 + 1] = -INFINITY;
        }
    } else if (lane == 0) {
        s_l[wid * 2] = -INFINITY;
        s_l[wid * 2 + 1] = -INFINITY;
    }
    __syncthreads();

    if (t == 0) {
        float m = s_l[0];
#pragma unroll
        for (int k = 1; k < 16; k++) m = fmaxf(m, s_l[k]);
        float sum = 0.f;
#pragma unroll
        for (int k = 0; k < 16; k++) sum += expf(s_l[k] - m);
        g_pm[blockIdx.x] = m;
        g_ps[blockIdx.x] = sum;
    }
}

// ---------------------------------------------------------------------------
// K6: fused log-sum-exp + subtract.
// ---------------------------------------------------------------------------
__global__ void __launch_bounds__(256)
k_finish(float* __restrict__ logits) {
    GDC_WAIT();
    __shared__ float red[256];
    int t = threadIdx.x;
    float m = -INFINITY;
    for (int i = t; i < NPART; i += 256) m = fmaxf(m, g_pm[i]);
    red[t] = m;
    __syncthreads();
#pragma unroll
    for (int o = 128; o; o >>= 1) {
        if (t < o) red[t] = fmaxf(red[t], red[t + o]);
        __syncthreads();
    }
    m = red[0];
    __syncthreads();
    float s = 0.f;
    for (int i = t; i < NPART; i += 256) s += g_ps[i] * expf(g_pm[i] - m);
    red[t] = s;
    __syncthreads();
#pragma unroll
    for (int o = 128; o; o >>= 1) {
        if (t < o) red[t] += red[t + o];
        __syncthreads();
    }
    __syncthreads();
    float lse = m + logf(red[0]);

    int idx = blockIdx.x * 256 + t;
    if (idx < VOC) logits[idx] -= lse;
}

// ---------------------------------------------------------------------------
// host: PDL launch helper
// ---------------------------------------------------------------------------
static void launch_pdl(const void* fn, dim3 grid, dim3 block, void** args) {
    cudaLaunchConfig_t cfg = {};
    cfg.gridDim = grid;
    cfg.blockDim = block;
    cfg.dynamicSmemBytes = 0;
    cfg.stream = 0;
    cudaLaunchAttribute at[1];
    at[0].id = cudaLaunchAttributeProgrammaticStreamSerialization;
    at[0].val.programmaticStreamSerializationAllowed = 1;
    cfg.attrs = at;
    cfg.numAttrs = 1;
    cudaLaunchKernelExC(&cfg, fn, args);
}

// ---------------------------------------------------------------------------
// Output layout: [log_probs(V) | h_new(2*H) | c_new(2*H) | attn_weights(L)]
// ---------------------------------------------------------------------------
extern "C" void kernel_launch(void* const* d_in, const int* in_sizes, int n_in,
                              void* d_out, int out_size) {
    const int*   tok    = (const int*)  d_in[0];
    const float* h0     = (const float*)d_in[1];
    const float* c0     = (const float*)d_in[2];
    const float* enc    = (const float*)d_in[3];
    const float* emb    = (const float*)d_in[4];
    const float* attn_w = (const float*)d_in[5];
    const float* attn_b = (const float*)d_in[6];
    const float* comb_w = (const float*)d_in[7];
    const float* comb_b = (const float*)d_in[8];
    const float* w_ih0  = (const float*)d_in[9];
    const float* w_hh0  = (const float*)d_in[10];
    const float* b_ih0  = (const float*)d_in[11];
    const float* b_hh0  = (const float*)d_in[12];
    const float* w_ih1  = (const float*)d_in[13];
    const float* w_hh1  = (const float*)d_in[14];
    const float* b_ih1  = (const float*)d_in[15];
    const float* b_hh1  = (const float*)d_in[16];
    const float* out_w  = (const float*)d_in[17];
    const float* out_b  = (const float*)d_in[18];

    float* out      = (float*)d_out;
    float* o_logp   = out;
    float* o_h      = out + VOC;
    float* o_c      = out + VOC + 2 * HID;
    float* o_attn   = out + VOC + 4 * HID;

    k_attn<<<1, 512>>>(tok, h0, emb, attn_w, attn_b, enc, o_attn);

    {
        void* args[] = {(void*)&comb_w, (void*)&comb_b};
        launch_pdl((const void*)k_comb, dim3(128), dim3(128), args);
    }
    {
        float* ho = o_h;
        float* co = o_c;
        void* args[] = {(void*)&h0, (void*)&c0, (void*)&w_ih0, (void*)&w_hh0,
                        (void*)&w_hh1, (void*)&b_ih0, (void*)&b_hh0, &ho, &co};
        launch_pdl((const void*)k_lstm_a, dim3(512), dim3(256), args);
    }
    {
        float* ho = o_h + HID;
        float* co = o_c + HID;
        void* args[] = {(void*)&h0, (void*)&c0, (void*)&w_ih1,
                        (void*)&b_ih1, (void*)&b_hh1, &ho, &co};
        launch_pdl((const void*)k_lstm_b, dim3(256), dim3(256), args);
    }
    {
        void* args[] = {(void*)&out_w, (void*)&out_b, (void*)&o_logp};
        launch_pdl((const void*)k_logits, dim3(NPART), dim3(256), args);
    }
    {
        void* args[] = {(void*)&o_logp};
        launch_pdl((const void*)k_finish, dim3((VOC + 255) / 256), dim3(256), args);
    }
}